// round 15
// baseline (speedup 1.0000x reference)
#include <cuda_runtime.h>
#include <math.h>
#include <stdint.h>

#define NN   10000
#define NE   80000
#define NB   64
#define NH   4
#define DH   256
#define HC   1024
#define FEATD 896

// uall column layout: [u(1024) | qw(1024) | skip(256)]
#define WALLN 2304
#define OFF_U    0
#define OFF_QW   1024
#define OFF_SKIP 2048

#define CAP  128  // per-target smem alpha capacity in edge_fused_k
#define RCAP 16   // per-target smem row-cache capacity (x/ea rows)
#define KSPLIT 2  // split-K slices for the wcomb GEMM

// ---------------- scratch ----------------------------------------------------
__device__ float g_x    [NN * DH];
__device__ float g_h    [NE * 128];
__device__ float g_ea   [NE * DH];
__device__ float g_wall [3][DH * WALLN];
__device__ float g_wst2 [3][2048 * DH];     // [Wv_stack ; We_stack] per layer
__device__ float g_uall [NN * WALLN];
__device__ float g_alpha[NE * NH];          // overflow-only (deg > CAP)
__device__ float g_wcomb[NN * 2048];        // [wxa(1024) | wea(1024)]
__device__ float g_part [8 * NB * 1024 > KSPLIT * NN * DH ? 8 * NB * 1024 : KSPLIT * NN * DH];
__device__ float g_feat [NB * FEATD];
__device__ float g_cnt  [NB];
__device__ float g_en1  [NB * 256];
__device__ float g_fc1  [NB * 1024];
__device__ int   g_deg  [NN];
__device__ int   g_off  [NN + 1];
__device__ int   g_cur  [NN];
__device__ int   g_perm [NE];

// ---------------- tf32 helpers -----------------------------------------------
__device__ __forceinline__ float f2tf32(float f)
{
    uint32_t u;
    asm("cvt.rna.tf32.f32 %0, %1;" : "=r"(u) : "f"(f));
    return __uint_as_float(u);
}

__device__ __forceinline__ void mma168(float& d0, float& d1, float& d2, float& d3,
                                       uint32_t a0, uint32_t a1, uint32_t a2, uint32_t a3,
                                       uint32_t b0, uint32_t b1)
{
    asm volatile(
        "mma.sync.aligned.m16n8k8.row.col.f32.tf32.tf32.f32 "
        "{%0,%1,%2,%3}, {%4,%5,%6,%7}, {%8,%9}, {%0,%1,%2,%3};"
        : "+f"(d0), "+f"(d1), "+f"(d2), "+f"(d3)
        : "r"(a0), "r"(a1), "r"(a2), "r"(a3), "r"(b0), "r"(b1));
}

// ---------------- tgemm: tf32 tensor-core GEMM (PROVEN round-12 version) -----
__global__ __launch_bounds__(256) void tgemm(
    const float* __restrict__ A, const float* __restrict__ B,
    const float* __restrict__ bias, float* __restrict__ C,
    int M, int K, int N, int lda, int ldb, int ldc, int flags,
    const float* __restrict__ addp, int ldadd, float scale, int kslices)
{
    __shared__ float As[2][128][20];
    __shared__ float Bs[2][16][132];

    const int tid    = threadIdx.x;
    const int lane   = tid & 31;
    const int warp   = tid >> 5;
    const int warpM  = warp >> 1;
    const int warpN  = warp & 1;
    const int rowW   = warpM * 32;
    const int colW   = warpN * 64;
    const int gid    = lane >> 2;
    const int tig    = lane & 3;
    const int row0   = blockIdx.x * 128;
    const int col0   = blockIdx.y * 128;

    const int kper   = K / kslices;
    const int nT     = kper / 16;
    const float* Ab  = A + (size_t)blockIdx.z * kper;
    const float* Bb  = B + (size_t)blockIdx.z * kper * ldb;
    float* Cb        = C + (size_t)blockIdx.z * M * ldc;

    float4 aReg[2], bReg[2];
    float acc[2][8][4];
#pragma unroll
    for (int mi = 0; mi < 2; mi++)
#pragma unroll
        for (int ni = 0; ni < 8; ni++)
#pragma unroll
            for (int r = 0; r < 4; r++) acc[mi][ni][r] = 0.f;

    auto fetch = [&](int kt) {
        int k0 = kt * 16;
#pragma unroll
        for (int i = 0; i < 2; i++) {
            int r = (tid >> 2) + 64 * i;
            int c = (tid & 3) * 4;
            int gr = row0 + r;
            aReg[i] = (gr < M) ? *(const float4*)(Ab + (size_t)gr * lda + k0 + c)
                               : make_float4(0.f, 0.f, 0.f, 0.f);
        }
#pragma unroll
        for (int i = 0; i < 2; i++) {
            int r = (tid >> 5) + 8 * i;
            int c = (tid & 31) * 4;
            int gc = col0 + c;
            bReg[i] = (gc < N) ? *(const float4*)(Bb + (size_t)(k0 + r) * ldb + gc)
                               : make_float4(0.f, 0.f, 0.f, 0.f);
        }
    };
    auto store = [&](int buf) {
#pragma unroll
        for (int i = 0; i < 2; i++) {
            int r = (tid >> 2) + 64 * i;
            int c = (tid & 3) * 4;
            As[buf][r][c + 0] = f2tf32(aReg[i].x);
            As[buf][r][c + 1] = f2tf32(aReg[i].y);
            As[buf][r][c + 2] = f2tf32(aReg[i].z);
            As[buf][r][c + 3] = f2tf32(aReg[i].w);
        }
#pragma unroll
        for (int i = 0; i < 2; i++) {
            int r = (tid >> 5) + 8 * i;
            int c = (tid & 31) * 4;
            float4 t;
            t.x = f2tf32(bReg[i].x);
            t.y = f2tf32(bReg[i].y);
            t.z = f2tf32(bReg[i].z);
            t.w = f2tf32(bReg[i].w);
            *(float4*)&Bs[buf][r][c] = t;
        }
    };

    fetch(0); store(0);
    if (nT > 1) fetch(1);
    __syncthreads();

    for (int t = 0; t < nT; t++) {
        int cur = t & 1;
#pragma unroll
        for (int k8 = 0; k8 < 16; k8 += 8) {
            uint32_t af[2][4];
#pragma unroll
            for (int mi = 0; mi < 2; mi++) {
                int r = rowW + mi * 16 + gid;
                af[mi][0] = __float_as_uint(As[cur][r    ][k8 + tig]);
                af[mi][1] = __float_as_uint(As[cur][r + 8][k8 + tig]);
                af[mi][2] = __float_as_uint(As[cur][r    ][k8 + tig + 4]);
                af[mi][3] = __float_as_uint(As[cur][r + 8][k8 + tig + 4]);
            }
            uint32_t bf[8][2];
#pragma unroll
            for (int ni = 0; ni < 8; ni++) {
                int c = colW + ni * 8 + gid;
                bf[ni][0] = __float_as_uint(Bs[cur][k8 + tig    ][c]);
                bf[ni][1] = __float_as_uint(Bs[cur][k8 + tig + 4][c]);
            }
#pragma unroll
            for (int mi = 0; mi < 2; mi++)
#pragma unroll
                for (int ni = 0; ni < 8; ni++)
                    mma168(acc[mi][ni][0], acc[mi][ni][1], acc[mi][ni][2], acc[mi][ni][3],
                           af[mi][0], af[mi][1], af[mi][2], af[mi][3],
                           bf[ni][0], bf[ni][1]);
        }
        if (t + 1 < nT) store((t + 1) & 1);
        if (t + 2 < nT) fetch(t + 2);
        __syncthreads();
    }

#pragma unroll
    for (int mi = 0; mi < 2; mi++) {
        int r0 = row0 + rowW + mi * 16 + gid;
#pragma unroll
        for (int ni = 0; ni < 8; ni++) {
            int c0 = col0 + colW + ni * 8 + tig * 2;
#pragma unroll
            for (int rr = 0; rr < 2; rr++) {
                int gr = r0 + rr * 8;
                if (gr >= M) continue;
#pragma unroll
                for (int cc = 0; cc < 2; cc++) {
                    int gc = c0 + cc;
                    if (gc >= N) continue;
                    float vv = acc[mi][ni][rr * 2 + cc];
                    if (bias) vv += bias[gc];
                    if (flags & 1) vv = vv > 0.f ? vv : 0.01f * vv;
                    if (addp) vv = vv * scale + addp[(size_t)gr * ldadd + gc];
                    Cb[(size_t)gr * ldc + gc] = vv;
                }
            }
        }
    }
}

__device__ __forceinline__ void atomicMaxF(float* addr, float v)
{
    if (v >= 0.f) atomicMax((int*)addr, __float_as_int(v));
    else          atomicMin((unsigned int*)addr, __float_as_uint(v));
}

// x = 0.25*(p0+p1) + skip  (skip lives in uall); optionally fused pooling
__global__ void combine4_k(const float* __restrict__ part,
                           const float* __restrict__ uall, float* __restrict__ x,
                           const int* __restrict__ batch, float* __restrict__ feat,
                           int do_pool)
{
    int i = blockIdx.x * blockDim.x + threadIdx.x;
    if (i >= NN * DH) return;
    int n = i >> 8, c = i & 255;
    float s = part[i] + part[NN * DH + i];
    float v = 0.25f * s + uall[(size_t)n * WALLN + OFF_SKIP + c];
    x[i] = v;
    if (do_pool) {
        int b = batch[n];
        atomicAdd(&feat[b * FEATD + 512 + c], v);
        atomicMaxF(&feat[b * FEATD + 256 + c], v);
    }
}

// dst = act(sum_z part[z] + bias)  over M*N elements
__global__ void combine_mlp_k(const float* __restrict__ part,
                              const float* __restrict__ bias, float* __restrict__ dst,
                              int M, int N, int slices, int act)
{
    int i = blockIdx.x * blockDim.x + threadIdx.x;
    if (i >= M * N) return;
    int c = i % N;
    float s = 0.f;
    for (int z = 0; z < slices; z++) s += part[(size_t)z * M * N + i];
    s += bias[c];
    if (act) s = s > 0.f ? s : 0.01f * s;
    dst[i] = s;
}

// ---------------- fp32 sgemm with optional split-K ---------------------------
__global__ void sgemm_k(const float* __restrict__ A, const float* __restrict__ B,
                        const float* __restrict__ bias, float* __restrict__ C,
                        int M, int K, int Nn, int ldc, int act, int kslices)
{
    __shared__ float As[8][128];
    __shared__ float Bs[8][128];
    const int tid = threadIdx.x;
    const int row0 = blockIdx.x * 128;
    const int col0 = blockIdx.y * 128;
    const int ty = tid >> 4;
    const int tx = tid & 15;

    const int kper = K / kslices;
    const float* Ab = A + (size_t)blockIdx.z * kper;
    const float* Bb = B + (size_t)blockIdx.z * kper * Nn;
    float* Cb       = C + (size_t)blockIdx.z * M * ldc;

    float acc[8][8];
#pragma unroll
    for (int i = 0; i < 8; i++)
#pragma unroll
        for (int j = 0; j < 8; j++) acc[i][j] = 0.f;

    for (int k0 = 0; k0 < kper; k0 += 8) {
#pragma unroll
        for (int i = 0; i < 4; i++) {
            int idx = tid + i * 256;
            int r = idx >> 3, c = idx & 7;
            int gr = row0 + r, gc = k0 + c;
            As[c][r] = (gr < M && gc < kper) ? Ab[(size_t)gr * K + gc] : 0.f;
        }
#pragma unroll
        for (int i = 0; i < 4; i++) {
            int idx = tid + i * 256;
            int r = idx >> 7, c = idx & 127;
            int gr = k0 + r, gc = col0 + c;
            Bs[r][c] = (gr < kper && gc < Nn) ? Bb[(size_t)gr * Nn + gc] : 0.f;
        }
        __syncthreads();
#pragma unroll
        for (int kk = 0; kk < 8; kk++) {
            float a[8], b[8];
#pragma unroll
            for (int i = 0; i < 8; i++) a[i] = As[kk][ty * 8 + i];
#pragma unroll
            for (int j = 0; j < 8; j++) b[j] = Bs[kk][tx * 8 + j];
#pragma unroll
            for (int i = 0; i < 8; i++)
#pragma unroll
                for (int j = 0; j < 8; j++) acc[i][j] += a[i] * b[j];
        }
        __syncthreads();
    }

#pragma unroll
    for (int i = 0; i < 8; i++) {
        int gr = row0 + ty * 8 + i;
        if (gr >= M) continue;
#pragma unroll
        for (int j = 0; j < 8; j++) {
            int gc = col0 + tx * 8 + j;
            if (gc >= Nn) continue;
            float v = acc[i][j];
            if (bias) v += bias[gc];
            if (act)  v = v > 0.f ? v : 0.01f * v;
            Cb[(size_t)gr * ldc + gc] = v;
        }
    }
}

// ---------------- edge MLP layer 1 -------------------------------------------
__global__ __launch_bounds__(256) void edge1_k(const float* __restrict__ ea_attr,
                                               const float* __restrict__ w1,
                                               const float* __restrict__ b1,
                                               float* __restrict__ h)
{
    __shared__ float sw1[14 * 128];
    __shared__ float sb1[128];
    int tid = threadIdx.x;
    for (int i = tid; i < 14 * 128; i += 256) sw1[i] = w1[i];
    if (tid < 128) sb1[tid] = b1[tid];
    __syncthreads();

    int e = blockIdx.x * 2 + (tid >> 7);
    int n = tid & 127;
    const float* arow = ea_attr + (size_t)e * 14;
    float acc = sb1[n];
#pragma unroll
    for (int k = 0; k < 14; k++) acc += arow[k] * sw1[k * 128 + n];
    acc = acc > 0.f ? acc : 0.01f * acc;
    h[(size_t)e * 128 + n] = acc;
}

// ---------------- weight prep: Wqk_h=Wq_h@Wk_h^T, Wqe_h=Wq_h@We_h^T ----------
__global__ __launch_bounds__(256) void wprep_k(const float* __restrict__ wq_l,
                                               const float* __restrict__ wk_l,
                                               const float* __restrict__ we_l,
                                               float* __restrict__ wall)
{
    int z = blockIdx.z;
    int h = z >> 1, which = z & 1;
    const float* A = wq_l + h * 256;
    const float* B = (which ? we_l : wk_l) + h * 256;
    float* C = wall + (which ? OFF_QW : OFF_U) + h * 256;

    __shared__ float As[16][64];
    __shared__ float Bs[16][64];
    int tid = threadIdx.x;
    int ty = tid >> 4, tx = tid & 15;
    float acc[4][4];
#pragma unroll
    for (int i = 0; i < 4; i++)
#pragma unroll
        for (int j = 0; j < 4; j++) acc[i][j] = 0.f;

    for (int k0 = 0; k0 < 256; k0 += 16) {
        int m = tid >> 2, kq = tid & 3;
        float4 a4 = *(const float4*)(A + (size_t)(blockIdx.x * 64 + m) * 1024 + k0 + kq * 4);
        As[kq * 4 + 0][m] = a4.x; As[kq * 4 + 1][m] = a4.y;
        As[kq * 4 + 2][m] = a4.z; As[kq * 4 + 3][m] = a4.w;
        float4 b4 = *(const float4*)(B + (size_t)(blockIdx.y * 64 + m) * 1024 + k0 + kq * 4);
        Bs[kq * 4 + 0][m] = b4.x; Bs[kq * 4 + 1][m] = b4.y;
        Bs[kq * 4 + 2][m] = b4.z; Bs[kq * 4 + 3][m] = b4.w;
        __syncthreads();
#pragma unroll
        for (int kk = 0; kk < 16; kk++) {
            float a[4], b[4];
#pragma unroll
            for (int i = 0; i < 4; i++) a[i] = As[kk][ty * 4 + i];
#pragma unroll
            for (int j = 0; j < 4; j++) b[j] = Bs[kk][tx * 4 + j];
#pragma unroll
            for (int i = 0; i < 4; i++)
#pragma unroll
                for (int j = 0; j < 4; j++) acc[i][j] += a[i] * b[j];
        }
        __syncthreads();
    }
#pragma unroll
    for (int i = 0; i < 4; i++)
#pragma unroll
        for (int j = 0; j < 4; j++)
            C[(size_t)(blockIdx.x * 64 + ty * 4 + i) * WALLN + blockIdx.y * 64 + tx * 4 + j] = acc[i][j];
}

// wall[:,2048:2304]=wskip;  wst2[h*256+d,c]=wv[d,h*256+c]; wst2[1024+h*256+d,c]=we[d,h*256+c]
__global__ void pack_k(const float* __restrict__ wv_l, const float* __restrict__ ws_l,
                       const float* __restrict__ we_l, float* __restrict__ wall,
                       float* __restrict__ wst2)
{
    int i = blockIdx.x * blockDim.x + threadIdx.x;
    if (i < DH * DH) {
        int r = i >> 8, c = i & 255;
        wall[(size_t)r * WALLN + OFF_SKIP + c] = ws_l[r * 256 + c];
    }
    if (i < 2048 * DH) {
        int r = i >> 8, c = i & 255;
        if (r < 1024) {
            int h = r >> 8, d = r & 255;
            wst2[i] = wv_l[d * 1024 + h * 256 + c];
        } else {
            int r2 = r - 1024;
            int h = r2 >> 8, d = r2 & 255;
            wst2[i] = we_l[d * 1024 + h * 256 + c];
        }
    }
}

// ---------------- CSR build --------------------------------------------------
__global__ void zero_int_k(int* p, int n)
{
    int i = blockIdx.x * blockDim.x + threadIdx.x;
    if (i < n) p[i] = 0;
}

__global__ void deg_k(const int* __restrict__ tgt, int* __restrict__ deg)
{
    int e = blockIdx.x * blockDim.x + threadIdx.x;
    if (e < NE) atomicAdd(&deg[tgt[e]], 1);
}

__global__ __launch_bounds__(1024) void scan_k(const int* __restrict__ deg,
                                               int* __restrict__ off)
{
    __shared__ int part[1024];
    int tid = threadIdx.x;
    const int per = (NN + 1023) / 1024;
    int base = tid * per;
    int s = 0;
    for (int i = 0; i < per; i++) {
        int idx = base + i;
        if (idx < NN) s += deg[idx];
    }
    part[tid] = s;
    __syncthreads();
    for (int o = 1; o < 1024; o <<= 1) {
        int v = (tid >= o) ? part[tid - o] : 0;
        __syncthreads();
        part[tid] += v;
        __syncthreads();
    }
    int run = part[tid] - s;
    for (int i = 0; i < per; i++) {
        int idx = base + i;
        if (idx < NN) { off[idx] = run; run += deg[idx]; }
    }
    if (tid == 1023) off[NN] = part[1023];
}

__global__ void fillperm_k(const int* __restrict__ tgt, int* __restrict__ cur,
                           int* __restrict__ perm)
{
    int e = blockIdx.x * blockDim.x + threadIdx.x;
    if (e >= NE) return;
    int pos = atomicAdd(&cur[tgt[e]], 1);
    perm[pos] = e;
}

// ---------------- helpers ----------------------------------------------------
__global__ void fill_k(float* p, float v, int n)
{
    int i = blockIdx.x * blockDim.x + threadIdx.x;
    if (i < n) p[i] = v;
}

// vectorized embedding: one float4 per thread
__global__ void embed_k(const int* __restrict__ ids, const float* __restrict__ emb,
                        float* __restrict__ x)
{
    int i = blockIdx.x * blockDim.x + threadIdx.x;
    if (i >= NN * 64) return;
    int n = i >> 6, c4 = i & 63;
    ((float4*)x)[i] = ((const float4*)(emb + (size_t)ids[n] * DH))[c4];
}

// ---------------- fused per-target edge pipeline -----------------------------
__global__ __launch_bounds__(256) void edge_fused_k(
    const int* __restrict__ off, const int* __restrict__ perm,
    const int* __restrict__ src, const float* __restrict__ uall,
    const float* __restrict__ x, const float* __restrict__ ea,
    float* __restrict__ galpha, float* __restrict__ wcomb)
{
    __shared__ float su[1024];
    __shared__ float sqw[1024];
    __shared__ float sx[RCAP * 256];
    __shared__ float se[RCAP * 256];
    __shared__ float sal[CAP * 4];
    __shared__ int   sed[CAP];
    __shared__ int   ssrc[CAP];

    const int t   = blockIdx.x;
    const int tid = threadIdx.x;
    const int b   = off[t];
    const int deg = off[t + 1] - b;

    const float* ub = uall + (size_t)t * WALLN;
    ((float4*)su)[tid]  = ((const float4*)(ub + OFF_U))[tid];
    ((float4*)sqw)[tid] = ((const float4*)(ub + OFF_QW))[tid];
    __syncthreads();

    const int warp = tid >> 5, lane = tid & 31;
    for (int j = warp; j < deg; j += 8) {
        int e = perm[b + j];
        int s = src[e];
        if (lane == 0 && j < CAP) { sed[j] = e; ssrc[j] = s; }
        const float4* xp = (const float4*)(x + (size_t)s * 256);
        const float4* ep = (const float4*)(ea + (size_t)e * 256);
        float4 xv0 = xp[lane], xv1 = xp[lane + 32];
        float4 ev0 = ep[lane], ev1 = ep[lane + 32];
        if (j < RCAP) {
            ((float4*)(sx + j * 256))[lane]      = xv0;
            ((float4*)(sx + j * 256))[lane + 32] = xv1;
            ((float4*)(se + j * 256))[lane]      = ev0;
            ((float4*)(se + j * 256))[lane + 32] = ev1;
        }
        float a[4];
#pragma unroll
        for (int h = 0; h < 4; h++) {
            const float4* up = (const float4*)(su + h * 256);
            const float4* qp = (const float4*)(sqw + h * 256);
            float4 u0 = up[lane], u1 = up[lane + 32];
            float4 q0 = qp[lane], q1 = qp[lane + 32];
            float acc = u0.x * xv0.x + u0.y * xv0.y + u0.z * xv0.z + u0.w * xv0.w
                      + u1.x * xv1.x + u1.y * xv1.y + u1.z * xv1.z + u1.w * xv1.w
                      + q0.x * ev0.x + q0.y * ev0.y + q0.z * ev0.z + q0.w * ev0.w
                      + q1.x * ev1.x + q1.y * ev1.y + q1.z * ev1.z + q1.w * ev1.w;
#pragma unroll
            for (int o = 16; o; o >>= 1) acc += __shfl_xor_sync(0xffffffffu, acc, o);
            a[h] = acc * 0.0625f;
        }
        if (lane == 0) {
            if (j < CAP) {
                sal[j * 4 + 0] = a[0]; sal[j * 4 + 1] = a[1];
                sal[j * 4 + 2] = a[2]; sal[j * 4 + 3] = a[3];
            } else {
                galpha[e * 4 + 0] = a[0]; galpha[e * 4 + 1] = a[1];
                galpha[e * 4 + 2] = a[2]; galpha[e * 4 + 3] = a[3];
            }
        }
    }
    __syncthreads();

    if (tid < 4 && deg > 0) {
        int h = tid;
        float mx = -INFINITY;
        for (int j = 0; j < deg; j++) {
            float v = (j < CAP) ? sal[j * 4 + h] : galpha[perm[b + j] * 4 + h];
            mx = fmaxf(mx, v);
        }
        float ssum = 0.f;
        for (int j = 0; j < deg; j++) {
            float v = (j < CAP) ? sal[j * 4 + h] : galpha[perm[b + j] * 4 + h];
            ssum += __expf(v - mx);
        }
        float inv = 1.f / (ssum + 1e-16f);
        for (int j = 0; j < deg; j++) {
            if (j < CAP) {
                sal[j * 4 + h] = __expf(sal[j * 4 + h] - mx) * inv;
            } else {
                int e = perm[b + j];
                galpha[e * 4 + h] = __expf(galpha[e * 4 + h] - mx) * inv;
            }
        }
    }
    __syncthreads();

    const int d = tid;
    float aX[4] = {0.f, 0.f, 0.f, 0.f};
    float aE[4] = {0.f, 0.f, 0.f, 0.f};

    for (int j = 0; j < deg; j++) {
        float a0, a1, a2, a3;
        if (j < CAP) {
            a0 = sal[j * 4 + 0]; a1 = sal[j * 4 + 1];
            a2 = sal[j * 4 + 2]; a3 = sal[j * 4 + 3];
        } else {
            int e = perm[b + j];
            a0 = galpha[e * 4 + 0]; a1 = galpha[e * 4 + 1];
            a2 = galpha[e * 4 + 2]; a3 = galpha[e * 4 + 3];
        }
        float xv, ev;
        if (j < RCAP) {
            xv = sx[j * 256 + d];
            ev = se[j * 256 + d];
        } else {
            int e = (j < CAP) ? sed[j] : perm[b + j];
            int s = (j < CAP) ? ssrc[j] : src[e];
            xv = x[(size_t)s * 256 + d];
            ev = ea[(size_t)e * 256 + d];
        }
        aX[0] += a0 * xv; aX[1] += a1 * xv; aX[2] += a2 * xv; aX[3] += a3 * xv;
        aE[0] += a0 * ev; aE[1] += a1 * ev; aE[2] += a2 * ev; aE[3] += a3 * ev;
    }
    float* wrow = wcomb + (size_t)t * 2048;
#pragma unroll
    for (int h = 0; h < 4; h++) {
        wrow[h * 256 + d]        = aX[h];
        wrow[1024 + h * 256 + d] = aE[h];
    }
}

__global__ void cnt_k(const int* __restrict__ batch, float* __restrict__ cnt)
{
    int n = blockIdx.x * blockDim.x + threadIdx.x;
    if (n < NN) atomicAdd(&cnt[batch[n]], 1.f);
}

__global__ void pool_init_k(float* __restrict__ feat)
{
    int i = blockIdx.x * blockDim.x + threadIdx.x;
    if (i >= NB * 512) return;
    int b = i >> 9, c = i & 511;
    feat[b * FEATD + 256 + c] = (c < 256) ? __int_as_float(0xff800000u) : 0.f;
}

__global__ void meanpool_k(float* __restrict__ feat, const float* __restrict__ cnt)
{
    int i = blockIdx.x * blockDim.x + threadIdx.x;
    if (i >= NB * 256) return;
    int b = i >> 8, c = i & 255;
    feat[b * FEATD + c] = feat[b * FEATD + 512 + c] / cnt[b];
}

// ---------------- launch -----------------------------------------------------
static inline dim3 g128(int M, int Nn) { return dim3((M + 127) / 128, (Nn + 127) / 128); }

extern "C" void kernel_launch(void* const* d_in, const int* in_sizes, int n_in,
                              void* d_out, int out_size)
{
    const int*   x_ids    = (const int*)  d_in[0];
    const int*   eidx     = (const int*)  d_in[1];
    const int*   batch    = (const int*)  d_in[2];
    const float* edge_attr= (const float*)d_in[3];
    const float* energies = (const float*)d_in[4];
    const float* node_emb = (const float*)d_in[5];
    const float* ew1      = (const float*)d_in[6];
    const float* eb1      = (const float*)d_in[7];
    const float* ew2      = (const float*)d_in[8];
    const float* eb2      = (const float*)d_in[9];
    const float* wq       = (const float*)d_in[10];
    const float* wk       = (const float*)d_in[11];
    const float* wv       = (const float*)d_in[12];
    const float* we       = (const float*)d_in[13];
    const float* wskip    = (const float*)d_in[14];
    const float* fce_w1   = (const float*)d_in[15];
    const float* fce_b1   = (const float*)d_in[16];
    const float* fce_w2   = (const float*)d_in[17];
    const float* fce_b2   = (const float*)d_in[18];
    const float* fc_w1    = (const float*)d_in[19];
    const float* fc_b1    = (const float*)d_in[20];
    const float* fc_w2    = (const float*)d_in[21];
    const float* fc_b2    = (const float*)d_in[22];
    float* out = (float*)d_out;

    const int* src = eidx;
    const int* tgt = eidx + NE;

    float *x, *h, *ea, *uall, *alpha, *wcomb, *part, *feat, *cnt, *en1, *fc1;
    float *wallb, *wst2b;
    int *deg, *off, *cur, *perm;
    cudaGetSymbolAddress((void**)&x,     g_x);
    cudaGetSymbolAddress((void**)&h,     g_h);
    cudaGetSymbolAddress((void**)&ea,    g_ea);
    cudaGetSymbolAddress((void**)&wallb, g_wall);
    cudaGetSymbolAddress((void**)&wst2b, g_wst2);
    cudaGetSymbolAddress((void**)&uall,  g_uall);
    cudaGetSymbolAddress((void**)&alpha, g_alpha);
    cudaGetSymbolAddress((void**)&wcomb, g_wcomb);
    cudaGetSymbolAddress((void**)&part,  g_part);
    cudaGetSymbolAddress((void**)&feat,  g_feat);
    cudaGetSymbolAddress((void**)&cnt,   g_cnt);
    cudaGetSymbolAddress((void**)&en1,   g_en1);
    cudaGetSymbolAddress((void**)&fc1,   g_fc1);
    cudaGetSymbolAddress((void**)&deg,   g_deg);
    cudaGetSymbolAddress((void**)&off,   g_off);
    cudaGetSymbolAddress((void**)&cur,   g_cur);
    cudaGetSymbolAddress((void**)&perm,  g_perm);

    float* wall[3]  = { wallb, wallb + (size_t)DH * WALLN, wallb + 2 * (size_t)DH * WALLN };
    float* wst2[3]  = { wst2b, wst2b + (size_t)2048 * DH,  wst2b + 2 * (size_t)2048 * DH };

    cudaStream_t s2, s3;
    cudaStreamCreateWithFlags(&s2, cudaStreamNonBlocking);
    cudaStreamCreateWithFlags(&s3, cudaStreamNonBlocking);
    cudaEvent_t evFork, evL[3], evEA, evEN, evCSR, evPI;
    cudaEventCreateWithFlags(&evFork, cudaEventDisableTiming);
    for (int l = 0; l < 3; l++) cudaEventCreateWithFlags(&evL[l], cudaEventDisableTiming);
    cudaEventCreateWithFlags(&evEA, cudaEventDisableTiming);
    cudaEventCreateWithFlags(&evEN, cudaEventDisableTiming);
    cudaEventCreateWithFlags(&evCSR, cudaEventDisableTiming);
    cudaEventCreateWithFlags(&evPI, cudaEventDisableTiming);

    // main: node embedding
    embed_k<<<(NN * 64 + 255) / 256, 256>>>(x_ids, node_emb, x);
    cudaEventRecord(evFork, 0);
    cudaStreamWaitEvent(s2, evFork, 0);
    cudaStreamWaitEvent(s3, evFork, 0);

    // s2: layer-0 weight prep
    wprep_k<<<dim3(4, 4, 8), 256, 0, s2>>>(wq, wk, we, wall[0]);
    pack_k<<<(2048 * DH + 255) / 256, 256, 0, s2>>>(wv, wskip, we, wall[0], wst2[0]);
    cudaEventRecord(evL[0], s2);

    // main: uall layer 0
    cudaStreamWaitEvent(0, evL[0], 0);
    tgemm<<<g128(NN, WALLN), 256>>>(x, wall[0], nullptr, uall,
                                    NN, 256, WALLN, 256, WALLN, WALLN, 0,
                                    nullptr, 0, 1.f, 1);

    // s3: CSR build, then pooling preamble (batch-only dependencies)
    zero_int_k<<<(NN + 255) / 256, 256, 0, s3>>>(deg, NN);
    deg_k<<<(NE + 255) / 256, 256, 0, s3>>>(tgt, deg);
    scan_k<<<1, 1024, 0, s3>>>(deg, off);
    cudaMemcpyAsync(cur, off, NN * sizeof(int), cudaMemcpyDeviceToDevice, s3);
    fillperm_k<<<(NE + 255) / 256, 256, 0, s3>>>(tgt, cur, perm);
    cudaEventRecord(evCSR, s3);
    pool_init_k<<<(NB * 512 + 255) / 256, 256, 0, s3>>>(feat);
    fill_k<<<1, NB, 0, s3>>>(cnt, 0.f, NB);
    cnt_k<<<(NN + 255) / 256, 256, 0, s3>>>(batch, cnt);
    cudaEventRecord(evPI, s3);

    // s2: edge MLP chain, remaining weight preps, energies MLP
    edge1_k<<<NE / 2, 256, 0, s2>>>(edge_attr, ew1, eb1, h);
    tgemm<<<g128(NE, 256), 256, 0, s2>>>(h, ew2, eb2, ea, NE, 128, 256, 128, 256, 256, 0,
                                         nullptr, 0, 1.f, 1);
    cudaEventRecord(evEA, s2);
    for (int l = 1; l < 3; l++) {
        wprep_k<<<dim3(4, 4, 8), 256, 0, s2>>>(wq + (size_t)l * DH * HC,
                                               wk + (size_t)l * DH * HC,
                                               we + (size_t)l * DH * HC, wall[l]);
        pack_k<<<(2048 * DH + 255) / 256, 256, 0, s2>>>(wv + (size_t)l * DH * HC,
                                                        wskip + (size_t)l * DH * DH,
                                                        we + (size_t)l * DH * HC,
                                                        wall[l], wst2[l]);
        cudaEventRecord(evL[l], s2);
    }
    sgemm_k<<<g128(NB, 256), 256, 0, s2>>>(energies, fce_w1, fce_b1, en1,
                                           NB, 201, 256, 256, 1, 1);
    sgemm_k<<<g128(NB, 128), 256, 0, s2>>>(en1, fce_w2, fce_b2, feat + 768,
                                           NB, 256, 128, FEATD, 0, 1);
    cudaEventRecord(evEN, s2);

    // main: layers
    cudaStreamWaitEvent(0, evEA, 0);
    cudaStreamWaitEvent(0, evCSR, 0);
    for (int l = 0; l < 3; l++) {
        if (l > 0) {
            cudaStreamWaitEvent(0, evL[l], 0);
            tgemm<<<g128(NN, WALLN), 256>>>(x, wall[l], nullptr, uall,
                                            NN, 256, WALLN, 256, WALLN, WALLN, 0,
                                            nullptr, 0, 1.f, 1);
        }
        edge_fused_k<<<NN, 256>>>(off, perm, src, uall, x, ea, alpha, wcomb);
        {
            dim3 g = g128(NN, DH);
            g.z = KSPLIT;
            tgemm<<<g, 256>>>(wcomb, wst2[l], nullptr, part,
                              NN, 2048, 256, 2048, 256, 256, 0,
                              nullptr, 0, 1.f, KSPLIT);
        }
        if (l == 2) cudaStreamWaitEvent(0, evPI, 0);   // feat init + cnt ready
        combine4_k<<<(NN * DH + 255) / 256, 256>>>(part, uall, x, batch, feat,
                                                   l == 2 ? 1 : 0);
    }

    // pooling epilogue (sum/max already fused into last combine)
    meanpool_k<<<(NB * 256 + 255) / 256, 256>>>(feat, cnt);

    // final MLP (split-K both)
    cudaStreamWaitEvent(0, evEN, 0);
    {
        dim3 g1(1, 8, 4);
        tgemm<<<g1, 256>>>(feat, fc_w1, nullptr, part,
                           NB, FEATD, 1024, FEATD, 1024, 1024, 0,
                           nullptr, 0, 1.f, 4);
        combine_mlp_k<<<(NB * 1024 + 255) / 256, 256>>>(part, fc_b1, fc1,
                                                        NB, 1024, 4, 1);
        dim3 g2(1, 7, 8);
        sgemm_k<<<g2, 256>>>(fc1, fc_w2, nullptr, part,
                             NB, 1024, 804, 804, 0, 8);
        combine_mlp_k<<<(NB * 804 + 255) / 256, 256>>>(part, fc_b2, out,
                                                       NB, 804, 8, 0);
    }

    cudaEventDestroy(evFork);
    for (int l = 0; l < 3; l++) cudaEventDestroy(evL[l]);
    cudaEventDestroy(evEA);
    cudaEventDestroy(evEN);
    cudaEventDestroy(evCSR);
    cudaEventDestroy(evPI);
    cudaStreamDestroy(s2);
    cudaStreamDestroy(s3);
}

// round 16
// speedup vs baseline: 1.0362x; 1.0362x over previous
#include <cuda_runtime.h>
#include <math.h>
#include <stdint.h>

#define NN   10000
#define NE   80000
#define NB   64
#define NH   4
#define DH   256
#define HC   1024
#define FEATD 896

// uall column layout: [u(1024) | qw(1024) | skip(256)]
#define WALLN 2304
#define OFF_U    0
#define OFF_QW   1024
#define OFF_SKIP 2048

#define CAP  128  // per-target smem alpha capacity in edge_fused_k
#define RCAP 16   // per-target smem row-cache capacity (x/ea rows)
#define KSPLIT 4  // split-K slices for the wcomb GEMM (4 is optimal; 2 regressed)

// ---------------- scratch ----------------------------------------------------
__device__ float g_x    [NN * DH];
__device__ float g_h    [NE * 128];
__device__ float g_ea   [NE * DH];
__device__ float g_wall [3][DH * WALLN];
__device__ float g_wst2 [3][2048 * DH];     // [Wv_stack ; We_stack] per layer
__device__ float g_uall [NN * WALLN];
__device__ float g_alpha[NE * NH];          // overflow-only (deg > CAP)
__device__ float g_wcomb[NN * 2048];        // [wxa(1024) | wea(1024)]
__device__ float g_part [KSPLIT * NN * DH]; // split-K partials (reused by MLPs)
__device__ float g_feat [NB * FEATD];
__device__ float g_cnt  [NB];
__device__ float g_en1  [NB * 256];
__device__ float g_fc1  [NB * 1024];
__device__ int   g_deg  [NN];
__device__ int   g_off  [NN + 1];
__device__ int   g_cur  [NN];
__device__ int   g_perm [NE];

// ---------------- tf32 helpers -----------------------------------------------
__device__ __forceinline__ float f2tf32(float f)
{
    uint32_t u;
    asm("cvt.rna.tf32.f32 %0, %1;" : "=r"(u) : "f"(f));
    return __uint_as_float(u);
}

__device__ __forceinline__ void mma168(float& d0, float& d1, float& d2, float& d3,
                                       uint32_t a0, uint32_t a1, uint32_t a2, uint32_t a3,
                                       uint32_t b0, uint32_t b1)
{
    asm volatile(
        "mma.sync.aligned.m16n8k8.row.col.f32.tf32.tf32.f32 "
        "{%0,%1,%2,%3}, {%4,%5,%6,%7}, {%8,%9}, {%0,%1,%2,%3};"
        : "+f"(d0), "+f"(d1), "+f"(d2), "+f"(d3)
        : "r"(a0), "r"(a1), "r"(a2), "r"(a3), "r"(b0), "r"(b1));
}

// ---------------- tgemm: tf32 tensor-core GEMM (PROVEN round-12 version) -----
__global__ __launch_bounds__(256) void tgemm(
    const float* __restrict__ A, const float* __restrict__ B,
    const float* __restrict__ bias, float* __restrict__ C,
    int M, int K, int N, int lda, int ldb, int ldc, int flags,
    const float* __restrict__ addp, int ldadd, float scale, int kslices)
{
    __shared__ float As[2][128][20];
    __shared__ float Bs[2][16][132];

    const int tid    = threadIdx.x;
    const int lane   = tid & 31;
    const int warp   = tid >> 5;
    const int warpM  = warp >> 1;
    const int warpN  = warp & 1;
    const int rowW   = warpM * 32;
    const int colW   = warpN * 64;
    const int gid    = lane >> 2;
    const int tig    = lane & 3;
    const int row0   = blockIdx.x * 128;
    const int col0   = blockIdx.y * 128;

    const int kper   = K / kslices;
    const int nT     = kper / 16;
    const float* Ab  = A + (size_t)blockIdx.z * kper;
    const float* Bb  = B + (size_t)blockIdx.z * kper * ldb;
    float* Cb        = C + (size_t)blockIdx.z * M * ldc;

    float4 aReg[2], bReg[2];
    float acc[2][8][4];
#pragma unroll
    for (int mi = 0; mi < 2; mi++)
#pragma unroll
        for (int ni = 0; ni < 8; ni++)
#pragma unroll
            for (int r = 0; r < 4; r++) acc[mi][ni][r] = 0.f;

    auto fetch = [&](int kt) {
        int k0 = kt * 16;
#pragma unroll
        for (int i = 0; i < 2; i++) {
            int r = (tid >> 2) + 64 * i;
            int c = (tid & 3) * 4;
            int gr = row0 + r;
            aReg[i] = (gr < M) ? *(const float4*)(Ab + (size_t)gr * lda + k0 + c)
                               : make_float4(0.f, 0.f, 0.f, 0.f);
        }
#pragma unroll
        for (int i = 0; i < 2; i++) {
            int r = (tid >> 5) + 8 * i;
            int c = (tid & 31) * 4;
            int gc = col0 + c;
            bReg[i] = (gc < N) ? *(const float4*)(Bb + (size_t)(k0 + r) * ldb + gc)
                               : make_float4(0.f, 0.f, 0.f, 0.f);
        }
    };
    auto store = [&](int buf) {
#pragma unroll
        for (int i = 0; i < 2; i++) {
            int r = (tid >> 2) + 64 * i;
            int c = (tid & 3) * 4;
            As[buf][r][c + 0] = f2tf32(aReg[i].x);
            As[buf][r][c + 1] = f2tf32(aReg[i].y);
            As[buf][r][c + 2] = f2tf32(aReg[i].z);
            As[buf][r][c + 3] = f2tf32(aReg[i].w);
        }
#pragma unroll
        for (int i = 0; i < 2; i++) {
            int r = (tid >> 5) + 8 * i;
            int c = (tid & 31) * 4;
            float4 t;
            t.x = f2tf32(bReg[i].x);
            t.y = f2tf32(bReg[i].y);
            t.z = f2tf32(bReg[i].z);
            t.w = f2tf32(bReg[i].w);
            *(float4*)&Bs[buf][r][c] = t;
        }
    };

    fetch(0); store(0);
    if (nT > 1) fetch(1);
    __syncthreads();

    for (int t = 0; t < nT; t++) {
        int cur = t & 1;
#pragma unroll
        for (int k8 = 0; k8 < 16; k8 += 8) {
            uint32_t af[2][4];
#pragma unroll
            for (int mi = 0; mi < 2; mi++) {
                int r = rowW + mi * 16 + gid;
                af[mi][0] = __float_as_uint(As[cur][r    ][k8 + tig]);
                af[mi][1] = __float_as_uint(As[cur][r + 8][k8 + tig]);
                af[mi][2] = __float_as_uint(As[cur][r    ][k8 + tig + 4]);
                af[mi][3] = __float_as_uint(As[cur][r + 8][k8 + tig + 4]);
            }
            uint32_t bf[8][2];
#pragma unroll
            for (int ni = 0; ni < 8; ni++) {
                int c = colW + ni * 8 + gid;
                bf[ni][0] = __float_as_uint(Bs[cur][k8 + tig    ][c]);
                bf[ni][1] = __float_as_uint(Bs[cur][k8 + tig + 4][c]);
            }
#pragma unroll
            for (int mi = 0; mi < 2; mi++)
#pragma unroll
                for (int ni = 0; ni < 8; ni++)
                    mma168(acc[mi][ni][0], acc[mi][ni][1], acc[mi][ni][2], acc[mi][ni][3],
                           af[mi][0], af[mi][1], af[mi][2], af[mi][3],
                           bf[ni][0], bf[ni][1]);
        }
        if (t + 1 < nT) store((t + 1) & 1);
        if (t + 2 < nT) fetch(t + 2);
        __syncthreads();
    }

#pragma unroll
    for (int mi = 0; mi < 2; mi++) {
        int r0 = row0 + rowW + mi * 16 + gid;
#pragma unroll
        for (int ni = 0; ni < 8; ni++) {
            int c0 = col0 + colW + ni * 8 + tig * 2;
#pragma unroll
            for (int rr = 0; rr < 2; rr++) {
                int gr = r0 + rr * 8;
                if (gr >= M) continue;
#pragma unroll
                for (int cc = 0; cc < 2; cc++) {
                    int gc = c0 + cc;
                    if (gc >= N) continue;
                    float vv = acc[mi][ni][rr * 2 + cc];
                    if (bias) vv += bias[gc];
                    if (flags & 1) vv = vv > 0.f ? vv : 0.01f * vv;
                    if (addp) vv = vv * scale + addp[(size_t)gr * ldadd + gc];
                    Cb[(size_t)gr * ldc + gc] = vv;
                }
            }
        }
    }
}

__device__ __forceinline__ void atomicMaxF(float* addr, float v)
{
    if (v >= 0.f) atomicMax((int*)addr, __float_as_int(v));
    else          atomicMin((unsigned int*)addr, __float_as_uint(v));
}

// x = 0.25*(p0+p1+p2+p3) + skip  (skip lives in uall); optionally fused pooling
__global__ void combine4_k(const float* __restrict__ part,
                           const float* __restrict__ uall, float* __restrict__ x,
                           const int* __restrict__ batch, float* __restrict__ feat,
                           int do_pool)
{
    int i = blockIdx.x * blockDim.x + threadIdx.x;
    if (i >= NN * DH) return;
    int n = i >> 8, c = i & 255;
    float s = part[i] + part[NN * DH + i] + part[2 * NN * DH + i] + part[3 * NN * DH + i];
    float v = 0.25f * s + uall[(size_t)n * WALLN + OFF_SKIP + c];
    x[i] = v;
    if (do_pool) {
        int b = batch[n];
        atomicAdd(&feat[b * FEATD + 512 + c], v);
        atomicMaxF(&feat[b * FEATD + 256 + c], v);
    }
}

// dst = act(sum_z part[z] + bias)  over M*N elements
__global__ void combine_mlp_k(const float* __restrict__ part,
                              const float* __restrict__ bias, float* __restrict__ dst,
                              int M, int N, int slices, int act)
{
    int i = blockIdx.x * blockDim.x + threadIdx.x;
    if (i >= M * N) return;
    int c = i % N;
    float s = 0.f;
    for (int z = 0; z < slices; z++) s += part[(size_t)z * M * N + i];
    s += bias[c];
    if (act) s = s > 0.f ? s : 0.01f * s;
    dst[i] = s;
}

// ---------------- fp32 sgemm with optional split-K ---------------------------
__global__ void sgemm_k(const float* __restrict__ A, const float* __restrict__ B,
                        const float* __restrict__ bias, float* __restrict__ C,
                        int M, int K, int Nn, int ldc, int act, int kslices)
{
    __shared__ float As[8][128];
    __shared__ float Bs[8][128];
    const int tid = threadIdx.x;
    const int row0 = blockIdx.x * 128;
    const int col0 = blockIdx.y * 128;
    const int ty = tid >> 4;
    const int tx = tid & 15;

    const int kper = K / kslices;
    const float* Ab = A + (size_t)blockIdx.z * kper;
    const float* Bb = B + (size_t)blockIdx.z * kper * Nn;
    float* Cb       = C + (size_t)blockIdx.z * M * ldc;

    float acc[8][8];
#pragma unroll
    for (int i = 0; i < 8; i++)
#pragma unroll
        for (int j = 0; j < 8; j++) acc[i][j] = 0.f;

    for (int k0 = 0; k0 < kper; k0 += 8) {
#pragma unroll
        for (int i = 0; i < 4; i++) {
            int idx = tid + i * 256;
            int r = idx >> 3, c = idx & 7;
            int gr = row0 + r, gc = k0 + c;
            As[c][r] = (gr < M && gc < kper) ? Ab[(size_t)gr * K + gc] : 0.f;
        }
#pragma unroll
        for (int i = 0; i < 4; i++) {
            int idx = tid + i * 256;
            int r = idx >> 7, c = idx & 127;
            int gr = k0 + r, gc = col0 + c;
            Bs[r][c] = (gr < kper && gc < Nn) ? Bb[(size_t)gr * Nn + gc] : 0.f;
        }
        __syncthreads();
#pragma unroll
        for (int kk = 0; kk < 8; kk++) {
            float a[8], b[8];
#pragma unroll
            for (int i = 0; i < 8; i++) a[i] = As[kk][ty * 8 + i];
#pragma unroll
            for (int j = 0; j < 8; j++) b[j] = Bs[kk][tx * 8 + j];
#pragma unroll
            for (int i = 0; i < 8; i++)
#pragma unroll
                for (int j = 0; j < 8; j++) acc[i][j] += a[i] * b[j];
        }
        __syncthreads();
    }

#pragma unroll
    for (int i = 0; i < 8; i++) {
        int gr = row0 + ty * 8 + i;
        if (gr >= M) continue;
#pragma unroll
        for (int j = 0; j < 8; j++) {
            int gc = col0 + tx * 8 + j;
            if (gc >= Nn) continue;
            float v = acc[i][j];
            if (bias) v += bias[gc];
            if (act)  v = v > 0.f ? v : 0.01f * v;
            Cb[(size_t)gr * ldc + gc] = v;
        }
    }
}

// ---------------- edge MLP layer 1 -------------------------------------------
__global__ __launch_bounds__(256) void edge1_k(const float* __restrict__ ea_attr,
                                               const float* __restrict__ w1,
                                               const float* __restrict__ b1,
                                               float* __restrict__ h)
{
    __shared__ float sw1[14 * 128];
    __shared__ float sb1[128];
    int tid = threadIdx.x;
    for (int i = tid; i < 14 * 128; i += 256) sw1[i] = w1[i];
    if (tid < 128) sb1[tid] = b1[tid];
    __syncthreads();

    int e = blockIdx.x * 2 + (tid >> 7);
    int n = tid & 127;
    const float* arow = ea_attr + (size_t)e * 14;
    float acc = sb1[n];
#pragma unroll
    for (int k = 0; k < 14; k++) acc += arow[k] * sw1[k * 128 + n];
    acc = acc > 0.f ? acc : 0.01f * acc;
    h[(size_t)e * 128 + n] = acc;
}

// ---------------- weight prep: Wqk_h=Wq_h@Wk_h^T, Wqe_h=Wq_h@We_h^T ----------
__global__ __launch_bounds__(256) void wprep_k(const float* __restrict__ wq_l,
                                               const float* __restrict__ wk_l,
                                               const float* __restrict__ we_l,
                                               float* __restrict__ wall)
{
    int z = blockIdx.z;
    int h = z >> 1, which = z & 1;
    const float* A = wq_l + h * 256;
    const float* B = (which ? we_l : wk_l) + h * 256;
    float* C = wall + (which ? OFF_QW : OFF_U) + h * 256;

    __shared__ float As[16][64];
    __shared__ float Bs[16][64];
    int tid = threadIdx.x;
    int ty = tid >> 4, tx = tid & 15;
    float acc[4][4];
#pragma unroll
    for (int i = 0; i < 4; i++)
#pragma unroll
        for (int j = 0; j < 4; j++) acc[i][j] = 0.f;

    for (int k0 = 0; k0 < 256; k0 += 16) {
        int m = tid >> 2, kq = tid & 3;
        float4 a4 = *(const float4*)(A + (size_t)(blockIdx.x * 64 + m) * 1024 + k0 + kq * 4);
        As[kq * 4 + 0][m] = a4.x; As[kq * 4 + 1][m] = a4.y;
        As[kq * 4 + 2][m] = a4.z; As[kq * 4 + 3][m] = a4.w;
        float4 b4 = *(const float4*)(B + (size_t)(blockIdx.y * 64 + m) * 1024 + k0 + kq * 4);
        Bs[kq * 4 + 0][m] = b4.x; Bs[kq * 4 + 1][m] = b4.y;
        Bs[kq * 4 + 2][m] = b4.z; Bs[kq * 4 + 3][m] = b4.w;
        __syncthreads();
#pragma unroll
        for (int kk = 0; kk < 16; kk++) {
            float a[4], b[4];
#pragma unroll
            for (int i = 0; i < 4; i++) a[i] = As[kk][ty * 4 + i];
#pragma unroll
            for (int j = 0; j < 4; j++) b[j] = Bs[kk][tx * 4 + j];
#pragma unroll
            for (int i = 0; i < 4; i++)
#pragma unroll
                for (int j = 0; j < 4; j++) acc[i][j] += a[i] * b[j];
        }
        __syncthreads();
    }
#pragma unroll
    for (int i = 0; i < 4; i++)
#pragma unroll
        for (int j = 0; j < 4; j++)
            C[(size_t)(blockIdx.x * 64 + ty * 4 + i) * WALLN + blockIdx.y * 64 + tx * 4 + j] = acc[i][j];
}

// wall[:,2048:2304]=wskip;  wst2[h*256+d,c]=wv[d,h*256+c]; wst2[1024+h*256+d,c]=we[d,h*256+c]
__global__ void pack_k(const float* __restrict__ wv_l, const float* __restrict__ ws_l,
                       const float* __restrict__ we_l, float* __restrict__ wall,
                       float* __restrict__ wst2)
{
    int i = blockIdx.x * blockDim.x + threadIdx.x;
    if (i < DH * DH) {
        int r = i >> 8, c = i & 255;
        wall[(size_t)r * WALLN + OFF_SKIP + c] = ws_l[r * 256 + c];
    }
    if (i < 2048 * DH) {
        int r = i >> 8, c = i & 255;
        if (r < 1024) {
            int h = r >> 8, d = r & 255;
            wst2[i] = wv_l[d * 1024 + h * 256 + c];
        } else {
            int r2 = r - 1024;
            int h = r2 >> 8, d = r2 & 255;
            wst2[i] = we_l[d * 1024 + h * 256 + c];
        }
    }
}

// ---------------- CSR build --------------------------------------------------
__global__ void zero_int_k(int* p, int n)
{
    int i = blockIdx.x * blockDim.x + threadIdx.x;
    if (i < n) p[i] = 0;
}

__global__ void deg_k(const int* __restrict__ tgt, int* __restrict__ deg)
{
    int e = blockIdx.x * blockDim.x + threadIdx.x;
    if (e < NE) atomicAdd(&deg[tgt[e]], 1);
}

__global__ __launch_bounds__(1024) void scan_k(const int* __restrict__ deg,
                                               int* __restrict__ off)
{
    __shared__ int part[1024];
    int tid = threadIdx.x;
    const int per = (NN + 1023) / 1024;
    int base = tid * per;
    int s = 0;
    for (int i = 0; i < per; i++) {
        int idx = base + i;
        if (idx < NN) s += deg[idx];
    }
    part[tid] = s;
    __syncthreads();
    for (int o = 1; o < 1024; o <<= 1) {
        int v = (tid >= o) ? part[tid - o] : 0;
        __syncthreads();
        part[tid] += v;
        __syncthreads();
    }
    int run = part[tid] - s;
    for (int i = 0; i < per; i++) {
        int idx = base + i;
        if (idx < NN) { off[idx] = run; run += deg[idx]; }
    }
    if (tid == 1023) off[NN] = part[1023];
}

__global__ void fillperm_k(const int* __restrict__ tgt, int* __restrict__ cur,
                           int* __restrict__ perm)
{
    int e = blockIdx.x * blockDim.x + threadIdx.x;
    if (e >= NE) return;
    int pos = atomicAdd(&cur[tgt[e]], 1);
    perm[pos] = e;
}

// ---------------- helpers ----------------------------------------------------
__global__ void fill_k(float* p, float v, int n)
{
    int i = blockIdx.x * blockDim.x + threadIdx.x;
    if (i < n) p[i] = v;
}

// vectorized embedding: one float4 per thread
__global__ void embed_k(const int* __restrict__ ids, const float* __restrict__ emb,
                        float* __restrict__ x)
{
    int i = blockIdx.x * blockDim.x + threadIdx.x;
    if (i >= NN * 64) return;
    int n = i >> 6, c4 = i & 63;
    ((float4*)x)[i] = ((const float4*)(emb + (size_t)ids[n] * DH))[c4];
}

// ---------------- fused per-target edge pipeline -----------------------------
__global__ __launch_bounds__(256) void edge_fused_k(
    const int* __restrict__ off, const int* __restrict__ perm,
    const int* __restrict__ src, const float* __restrict__ uall,
    const float* __restrict__ x, const float* __restrict__ ea,
    float* __restrict__ galpha, float* __restrict__ wcomb)
{
    __shared__ float su[1024];
    __shared__ float sqw[1024];
    __shared__ float sx[RCAP * 256];
    __shared__ float se[RCAP * 256];
    __shared__ float sal[CAP * 4];
    __shared__ int   sed[CAP];
    __shared__ int   ssrc[CAP];

    const int t   = blockIdx.x;
    const int tid = threadIdx.x;
    const int b   = off[t];
    const int deg = off[t + 1] - b;

    const float* ub = uall + (size_t)t * WALLN;
    ((float4*)su)[tid]  = ((const float4*)(ub + OFF_U))[tid];
    ((float4*)sqw)[tid] = ((const float4*)(ub + OFF_QW))[tid];
    __syncthreads();

    const int warp = tid >> 5, lane = tid & 31;
    for (int j = warp; j < deg; j += 8) {
        int e = perm[b + j];
        int s = src[e];
        if (lane == 0 && j < CAP) { sed[j] = e; ssrc[j] = s; }
        const float4* xp = (const float4*)(x + (size_t)s * 256);
        const float4* ep = (const float4*)(ea + (size_t)e * 256);
        float4 xv0 = xp[lane], xv1 = xp[lane + 32];
        float4 ev0 = ep[lane], ev1 = ep[lane + 32];
        if (j < RCAP) {
            ((float4*)(sx + j * 256))[lane]      = xv0;
            ((float4*)(sx + j * 256))[lane + 32] = xv1;
            ((float4*)(se + j * 256))[lane]      = ev0;
            ((float4*)(se + j * 256))[lane + 32] = ev1;
        }
        float a[4];
#pragma unroll
        for (int h = 0; h < 4; h++) {
            const float4* up = (const float4*)(su + h * 256);
            const float4* qp = (const float4*)(sqw + h * 256);
            float4 u0 = up[lane], u1 = up[lane + 32];
            float4 q0 = qp[lane], q1 = qp[lane + 32];
            float acc = u0.x * xv0.x + u0.y * xv0.y + u0.z * xv0.z + u0.w * xv0.w
                      + u1.x * xv1.x + u1.y * xv1.y + u1.z * xv1.z + u1.w * xv1.w
                      + q0.x * ev0.x + q0.y * ev0.y + q0.z * ev0.z + q0.w * ev0.w
                      + q1.x * ev1.x + q1.y * ev1.y + q1.z * ev1.z + q1.w * ev1.w;
#pragma unroll
            for (int o = 16; o; o >>= 1) acc += __shfl_xor_sync(0xffffffffu, acc, o);
            a[h] = acc * 0.0625f;
        }
        if (lane == 0) {
            if (j < CAP) {
                sal[j * 4 + 0] = a[0]; sal[j * 4 + 1] = a[1];
                sal[j * 4 + 2] = a[2]; sal[j * 4 + 3] = a[3];
            } else {
                galpha[e * 4 + 0] = a[0]; galpha[e * 4 + 1] = a[1];
                galpha[e * 4 + 2] = a[2]; galpha[e * 4 + 3] = a[3];
            }
        }
    }
    __syncthreads();

    if (tid < 4 && deg > 0) {
        int h = tid;
        float mx = -INFINITY;
        for (int j = 0; j < deg; j++) {
            float v = (j < CAP) ? sal[j * 4 + h] : galpha[perm[b + j] * 4 + h];
            mx = fmaxf(mx, v);
        }
        float ssum = 0.f;
        for (int j = 0; j < deg; j++) {
            float v = (j < CAP) ? sal[j * 4 + h] : galpha[perm[b + j] * 4 + h];
            ssum += __expf(v - mx);
        }
        float inv = 1.f / (ssum + 1e-16f);
        for (int j = 0; j < deg; j++) {
            if (j < CAP) {
                sal[j * 4 + h] = __expf(sal[j * 4 + h] - mx) * inv;
            } else {
                int e = perm[b + j];
                galpha[e * 4 + h] = __expf(galpha[e * 4 + h] - mx) * inv;
            }
        }
    }
    __syncthreads();

    const int d = tid;
    float aX[4] = {0.f, 0.f, 0.f, 0.f};
    float aE[4] = {0.f, 0.f, 0.f, 0.f};

    for (int j = 0; j < deg; j++) {
        float a0, a1, a2, a3;
        if (j < CAP) {
            a0 = sal[j * 4 + 0]; a1 = sal[j * 4 + 1];
            a2 = sal[j * 4 + 2]; a3 = sal[j * 4 + 3];
        } else {
            int e = perm[b + j];
            a0 = galpha[e * 4 + 0]; a1 = galpha[e * 4 + 1];
            a2 = galpha[e * 4 + 2]; a3 = galpha[e * 4 + 3];
        }
        float xv, ev;
        if (j < RCAP) {
            xv = sx[j * 256 + d];
            ev = se[j * 256 + d];
        } else {
            int e = (j < CAP) ? sed[j] : perm[b + j];
            int s = (j < CAP) ? ssrc[j] : src[e];
            xv = x[(size_t)s * 256 + d];
            ev = ea[(size_t)e * 256 + d];
        }
        aX[0] += a0 * xv; aX[1] += a1 * xv; aX[2] += a2 * xv; aX[3] += a3 * xv;
        aE[0] += a0 * ev; aE[1] += a1 * ev; aE[2] += a2 * ev; aE[3] += a3 * ev;
    }
    float* wrow = wcomb + (size_t)t * 2048;
#pragma unroll
    for (int h = 0; h < 4; h++) {
        wrow[h * 256 + d]        = aX[h];
        wrow[1024 + h * 256 + d] = aE[h];
    }
}

__global__ void cnt_k(const int* __restrict__ batch, float* __restrict__ cnt)
{
    int n = blockIdx.x * blockDim.x + threadIdx.x;
    if (n < NN) atomicAdd(&cnt[batch[n]], 1.f);
}

__global__ void pool_init_k(float* __restrict__ feat)
{
    int i = blockIdx.x * blockDim.x + threadIdx.x;
    if (i >= NB * 512) return;
    int b = i >> 9, c = i & 511;
    feat[b * FEATD + 256 + c] = (c < 256) ? __int_as_float(0xff800000u) : 0.f;
}

__global__ void meanpool_k(float* __restrict__ feat, const float* __restrict__ cnt)
{
    int i = blockIdx.x * blockDim.x + threadIdx.x;
    if (i >= NB * 256) return;
    int b = i >> 8, c = i & 255;
    feat[b * FEATD + c] = feat[b * FEATD + 512 + c] / cnt[b];
}

// ---------------- launch -----------------------------------------------------
static inline dim3 g128(int M, int Nn) { return dim3((M + 127) / 128, (Nn + 127) / 128); }

extern "C" void kernel_launch(void* const* d_in, const int* in_sizes, int n_in,
                              void* d_out, int out_size)
{
    const int*   x_ids    = (const int*)  d_in[0];
    const int*   eidx     = (const int*)  d_in[1];
    const int*   batch    = (const int*)  d_in[2];
    const float* edge_attr= (const float*)d_in[3];
    const float* energies = (const float*)d_in[4];
    const float* node_emb = (const float*)d_in[5];
    const float* ew1      = (const float*)d_in[6];
    const float* eb1      = (const float*)d_in[7];
    const float* ew2      = (const float*)d_in[8];
    const float* eb2      = (const float*)d_in[9];
    const float* wq       = (const float*)d_in[10];
    const float* wk       = (const float*)d_in[11];
    const float* wv       = (const float*)d_in[12];
    const float* we       = (const float*)d_in[13];
    const float* wskip    = (const float*)d_in[14];
    const float* fce_w1   = (const float*)d_in[15];
    const float* fce_b1   = (const float*)d_in[16];
    const float* fce_w2   = (const float*)d_in[17];
    const float* fce_b2   = (const float*)d_in[18];
    const float* fc_w1    = (const float*)d_in[19];
    const float* fc_b1    = (const float*)d_in[20];
    const float* fc_w2    = (const float*)d_in[21];
    const float* fc_b2    = (const float*)d_in[22];
    float* out = (float*)d_out;

    const int* src = eidx;
    const int* tgt = eidx + NE;

    float *x, *h, *ea, *uall, *alpha, *wcomb, *part, *feat, *cnt, *en1, *fc1;
    float *wallb, *wst2b;
    int *deg, *off, *cur, *perm;
    cudaGetSymbolAddress((void**)&x,     g_x);
    cudaGetSymbolAddress((void**)&h,     g_h);
    cudaGetSymbolAddress((void**)&ea,    g_ea);
    cudaGetSymbolAddress((void**)&wallb, g_wall);
    cudaGetSymbolAddress((void**)&wst2b, g_wst2);
    cudaGetSymbolAddress((void**)&uall,  g_uall);
    cudaGetSymbolAddress((void**)&alpha, g_alpha);
    cudaGetSymbolAddress((void**)&wcomb, g_wcomb);
    cudaGetSymbolAddress((void**)&part,  g_part);
    cudaGetSymbolAddress((void**)&feat,  g_feat);
    cudaGetSymbolAddress((void**)&cnt,   g_cnt);
    cudaGetSymbolAddress((void**)&en1,   g_en1);
    cudaGetSymbolAddress((void**)&fc1,   g_fc1);
    cudaGetSymbolAddress((void**)&deg,   g_deg);
    cudaGetSymbolAddress((void**)&off,   g_off);
    cudaGetSymbolAddress((void**)&cur,   g_cur);
    cudaGetSymbolAddress((void**)&perm,  g_perm);

    float* wall[3]  = { wallb, wallb + (size_t)DH * WALLN, wallb + 2 * (size_t)DH * WALLN };
    float* wst2[3]  = { wst2b, wst2b + (size_t)2048 * DH,  wst2b + 2 * (size_t)2048 * DH };

    cudaStream_t s2, s3;
    cudaStreamCreateWithFlags(&s2, cudaStreamNonBlocking);
    cudaStreamCreateWithFlags(&s3, cudaStreamNonBlocking);
    cudaEvent_t evFork, evL[3], evEA, evEN, evCSR, evPI;
    cudaEventCreateWithFlags(&evFork, cudaEventDisableTiming);
    for (int l = 0; l < 3; l++) cudaEventCreateWithFlags(&evL[l], cudaEventDisableTiming);
    cudaEventCreateWithFlags(&evEA, cudaEventDisableTiming);
    cudaEventCreateWithFlags(&evEN, cudaEventDisableTiming);
    cudaEventCreateWithFlags(&evCSR, cudaEventDisableTiming);
    cudaEventCreateWithFlags(&evPI, cudaEventDisableTiming);

    // main: node embedding (vectorized)
    embed_k<<<(NN * 64 + 255) / 256, 256>>>(x_ids, node_emb, x);
    cudaEventRecord(evFork, 0);
    cudaStreamWaitEvent(s2, evFork, 0);
    cudaStreamWaitEvent(s3, evFork, 0);

    // s2: layer-0 weight prep
    wprep_k<<<dim3(4, 4, 8), 256, 0, s2>>>(wq, wk, we, wall[0]);
    pack_k<<<(2048 * DH + 255) / 256, 256, 0, s2>>>(wv, wskip, we, wall[0], wst2[0]);
    cudaEventRecord(evL[0], s2);

    // main: uall layer 0
    cudaStreamWaitEvent(0, evL[0], 0);
    tgemm<<<g128(NN, WALLN), 256>>>(x, wall[0], nullptr, uall,
                                    NN, 256, WALLN, 256, WALLN, WALLN, 0,
                                    nullptr, 0, 1.f, 1);

    // s3: CSR build, then pooling preamble (batch-only dependencies)
    zero_int_k<<<(NN + 255) / 256, 256, 0, s3>>>(deg, NN);
    deg_k<<<(NE + 255) / 256, 256, 0, s3>>>(tgt, deg);
    scan_k<<<1, 1024, 0, s3>>>(deg, off);
    cudaMemcpyAsync(cur, off, NN * sizeof(int), cudaMemcpyDeviceToDevice, s3);
    fillperm_k<<<(NE + 255) / 256, 256, 0, s3>>>(tgt, cur, perm);
    cudaEventRecord(evCSR, s3);
    pool_init_k<<<(NB * 512 + 255) / 256, 256, 0, s3>>>(feat);
    fill_k<<<1, NB, 0, s3>>>(cnt, 0.f, NB);
    cnt_k<<<(NN + 255) / 256, 256, 0, s3>>>(batch, cnt);
    cudaEventRecord(evPI, s3);

    // s2: edge MLP chain, remaining weight preps, energies MLP
    edge1_k<<<NE / 2, 256, 0, s2>>>(edge_attr, ew1, eb1, h);
    tgemm<<<g128(NE, 256), 256, 0, s2>>>(h, ew2, eb2, ea, NE, 128, 256, 128, 256, 256, 0,
                                         nullptr, 0, 1.f, 1);
    cudaEventRecord(evEA, s2);
    for (int l = 1; l < 3; l++) {
        wprep_k<<<dim3(4, 4, 8), 256, 0, s2>>>(wq + (size_t)l * DH * HC,
                                               wk + (size_t)l * DH * HC,
                                               we + (size_t)l * DH * HC, wall[l]);
        pack_k<<<(2048 * DH + 255) / 256, 256, 0, s2>>>(wv + (size_t)l * DH * HC,
                                                        wskip + (size_t)l * DH * DH,
                                                        we + (size_t)l * DH * HC,
                                                        wall[l], wst2[l]);
        cudaEventRecord(evL[l], s2);
    }
    sgemm_k<<<g128(NB, 256), 256, 0, s2>>>(energies, fce_w1, fce_b1, en1,
                                           NB, 201, 256, 256, 1, 1);
    sgemm_k<<<g128(NB, 128), 256, 0, s2>>>(en1, fce_w2, fce_b2, feat + 768,
                                           NB, 256, 128, FEATD, 0, 1);
    cudaEventRecord(evEN, s2);

    // main: layers
    cudaStreamWaitEvent(0, evEA, 0);
    cudaStreamWaitEvent(0, evCSR, 0);
    for (int l = 0; l < 3; l++) {
        if (l > 0) {
            cudaStreamWaitEvent(0, evL[l], 0);
            tgemm<<<g128(NN, WALLN), 256>>>(x, wall[l], nullptr, uall,
                                            NN, 256, WALLN, 256, WALLN, WALLN, 0,
                                            nullptr, 0, 1.f, 1);
        }
        edge_fused_k<<<NN, 256>>>(off, perm, src, uall, x, ea, alpha, wcomb);
        {
            dim3 g = g128(NN, DH);
            g.z = KSPLIT;
            tgemm<<<g, 256>>>(wcomb, wst2[l], nullptr, part,
                              NN, 2048, 256, 2048, 256, 256, 0,
                              nullptr, 0, 1.f, KSPLIT);
        }
        if (l == 2) cudaStreamWaitEvent(0, evPI, 0);   // feat init + cnt ready
        combine4_k<<<(NN * DH + 255) / 256, 256>>>(part, uall, x, batch, feat,
                                                   l == 2 ? 1 : 0);
    }

    // pooling epilogue (sum/max fused into last combine)
    meanpool_k<<<(NB * 256 + 255) / 256, 256>>>(feat, cnt);

    // final MLP (split-K both)
    cudaStreamWaitEvent(0, evEN, 0);
    {
        dim3 g1(1, 8, 4);
        tgemm<<<g1, 256>>>(feat, fc_w1, nullptr, part,
                           NB, FEATD, 1024, FEATD, 1024, 1024, 0,
                           nullptr, 0, 1.f, 4);
        combine_mlp_k<<<(NB * 1024 + 255) / 256, 256>>>(part, fc_b1, fc1,
                                                        NB, 1024, 4, 1);
        dim3 g2(1, 7, 8);
        sgemm_k<<<g2, 256>>>(fc1, fc_w2, nullptr, part,
                             NB, 1024, 804, 804, 0, 8);
        combine_mlp_k<<<(NB * 804 + 255) / 256, 256>>>(part, fc_b2, out,
                                                       NB, 804, 8, 0);
    }

    cudaEventDestroy(evFork);
    for (int l = 0; l < 3; l++) cudaEventDestroy(evL[l]);
    cudaEventDestroy(evEA);
    cudaEventDestroy(evEN);
    cudaEventDestroy(evCSR);
    cudaEventDestroy(evPI);
    cudaStreamDestroy(s2);
    cudaStreamDestroy(s3);
}

// round 17
// speedup vs baseline: 1.0587x; 1.0218x over previous
#include <cuda_runtime.h>
#include <math.h>
#include <stdint.h>

#define NN   10000
#define NE   80000
#define NB   64
#define NH   4
#define DH   256
#define HC   1024
#define FEATD 896

// uall column layout: [u(1024) | qw(1024) | skip(256)]
#define WALLN 2304
#define OFF_U    0
#define OFF_QW   1024
#define OFF_SKIP 2048

#define CAP  128  // per-target smem alpha capacity in edge_fused_k
#define RCAP 16   // per-target smem row-cache capacity (x/ea rows)
#define KSPLIT 4  // split-K slices for the wcomb GEMM (4 is optimal; 2 regressed)

// ---------------- scratch ----------------------------------------------------
__device__ float g_x    [NN * DH];
__device__ float g_h    [NE * 128];
__device__ float g_ea   [NE * DH];
__device__ float g_wall [3][DH * WALLN];
__device__ float g_wst2 [3][2048 * DH];     // [Wv_stack ; We_stack] per layer
__device__ float g_uall [NN * WALLN];
__device__ float g_alpha[NE * NH];          // overflow-only (deg > CAP)
__device__ float g_wcomb[NN * 2048];        // [wxa(1024) | wea(1024)]
__device__ float g_part [KSPLIT * NN * DH]; // split-K partials (reused by MLPs)
__device__ float g_feat [NB * FEATD];
__device__ float g_cnt  [NB];
__device__ float g_en1  [NB * 256];
__device__ float g_fc1  [NB * 1024];
__device__ int   g_deg  [NN];
__device__ int   g_off  [NN + 1];
__device__ int   g_cur  [NN];
__device__ int   g_perm [NE];

// ---------------- tf32 helpers -----------------------------------------------
__device__ __forceinline__ float f2tf32(float f)
{
    uint32_t u;
    asm("cvt.rna.tf32.f32 %0, %1;" : "=r"(u) : "f"(f));
    return __uint_as_float(u);
}

__device__ __forceinline__ void mma168(float& d0, float& d1, float& d2, float& d3,
                                       uint32_t a0, uint32_t a1, uint32_t a2, uint32_t a3,
                                       uint32_t b0, uint32_t b1)
{
    asm volatile(
        "mma.sync.aligned.m16n8k8.row.col.f32.tf32.tf32.f32 "
        "{%0,%1,%2,%3}, {%4,%5,%6,%7}, {%8,%9}, {%0,%1,%2,%3};"
        : "+f"(d0), "+f"(d1), "+f"(d2), "+f"(d3)
        : "r"(a0), "r"(a1), "r"(a2), "r"(a3), "r"(b0), "r"(b1));
}

// ---------------- tgemm: tf32 tensor-core GEMM (PROVEN round-12 version) -----
__global__ __launch_bounds__(256) void tgemm(
    const float* __restrict__ A, const float* __restrict__ B,
    const float* __restrict__ bias, float* __restrict__ C,
    int M, int K, int N, int lda, int ldb, int ldc, int flags,
    const float* __restrict__ addp, int ldadd, float scale, int kslices)
{
    __shared__ float As[2][128][20];
    __shared__ float Bs[2][16][132];

    const int tid    = threadIdx.x;
    const int lane   = tid & 31;
    const int warp   = tid >> 5;
    const int warpM  = warp >> 1;
    const int warpN  = warp & 1;
    const int rowW   = warpM * 32;
    const int colW   = warpN * 64;
    const int gid    = lane >> 2;
    const int tig    = lane & 3;
    const int row0   = blockIdx.x * 128;
    const int col0   = blockIdx.y * 128;

    const int kper   = K / kslices;
    const int nT     = kper / 16;
    const float* Ab  = A + (size_t)blockIdx.z * kper;
    const float* Bb  = B + (size_t)blockIdx.z * kper * ldb;
    float* Cb        = C + (size_t)blockIdx.z * M * ldc;

    float4 aReg[2], bReg[2];
    float acc[2][8][4];
#pragma unroll
    for (int mi = 0; mi < 2; mi++)
#pragma unroll
        for (int ni = 0; ni < 8; ni++)
#pragma unroll
            for (int r = 0; r < 4; r++) acc[mi][ni][r] = 0.f;

    auto fetch = [&](int kt) {
        int k0 = kt * 16;
#pragma unroll
        for (int i = 0; i < 2; i++) {
            int r = (tid >> 2) + 64 * i;
            int c = (tid & 3) * 4;
            int gr = row0 + r;
            aReg[i] = (gr < M) ? *(const float4*)(Ab + (size_t)gr * lda + k0 + c)
                               : make_float4(0.f, 0.f, 0.f, 0.f);
        }
#pragma unroll
        for (int i = 0; i < 2; i++) {
            int r = (tid >> 5) + 8 * i;
            int c = (tid & 31) * 4;
            int gc = col0 + c;
            bReg[i] = (gc < N) ? *(const float4*)(Bb + (size_t)(k0 + r) * ldb + gc)
                               : make_float4(0.f, 0.f, 0.f, 0.f);
        }
    };
    auto store = [&](int buf) {
#pragma unroll
        for (int i = 0; i < 2; i++) {
            int r = (tid >> 2) + 64 * i;
            int c = (tid & 3) * 4;
            As[buf][r][c + 0] = f2tf32(aReg[i].x);
            As[buf][r][c + 1] = f2tf32(aReg[i].y);
            As[buf][r][c + 2] = f2tf32(aReg[i].z);
            As[buf][r][c + 3] = f2tf32(aReg[i].w);
        }
#pragma unroll
        for (int i = 0; i < 2; i++) {
            int r = (tid >> 5) + 8 * i;
            int c = (tid & 31) * 4;
            float4 t;
            t.x = f2tf32(bReg[i].x);
            t.y = f2tf32(bReg[i].y);
            t.z = f2tf32(bReg[i].z);
            t.w = f2tf32(bReg[i].w);
            *(float4*)&Bs[buf][r][c] = t;
        }
    };

    fetch(0); store(0);
    if (nT > 1) fetch(1);
    __syncthreads();

    for (int t = 0; t < nT; t++) {
        int cur = t & 1;
#pragma unroll
        for (int k8 = 0; k8 < 16; k8 += 8) {
            uint32_t af[2][4];
#pragma unroll
            for (int mi = 0; mi < 2; mi++) {
                int r = rowW + mi * 16 + gid;
                af[mi][0] = __float_as_uint(As[cur][r    ][k8 + tig]);
                af[mi][1] = __float_as_uint(As[cur][r + 8][k8 + tig]);
                af[mi][2] = __float_as_uint(As[cur][r    ][k8 + tig + 4]);
                af[mi][3] = __float_as_uint(As[cur][r + 8][k8 + tig + 4]);
            }
            uint32_t bf[8][2];
#pragma unroll
            for (int ni = 0; ni < 8; ni++) {
                int c = colW + ni * 8 + gid;
                bf[ni][0] = __float_as_uint(Bs[cur][k8 + tig    ][c]);
                bf[ni][1] = __float_as_uint(Bs[cur][k8 + tig + 4][c]);
            }
#pragma unroll
            for (int mi = 0; mi < 2; mi++)
#pragma unroll
                for (int ni = 0; ni < 8; ni++)
                    mma168(acc[mi][ni][0], acc[mi][ni][1], acc[mi][ni][2], acc[mi][ni][3],
                           af[mi][0], af[mi][1], af[mi][2], af[mi][3],
                           bf[ni][0], bf[ni][1]);
        }
        if (t + 1 < nT) store((t + 1) & 1);
        if (t + 2 < nT) fetch(t + 2);
        __syncthreads();
    }

#pragma unroll
    for (int mi = 0; mi < 2; mi++) {
        int r0 = row0 + rowW + mi * 16 + gid;
#pragma unroll
        for (int ni = 0; ni < 8; ni++) {
            int c0 = col0 + colW + ni * 8 + tig * 2;
#pragma unroll
            for (int rr = 0; rr < 2; rr++) {
                int gr = r0 + rr * 8;
                if (gr >= M) continue;
#pragma unroll
                for (int cc = 0; cc < 2; cc++) {
                    int gc = c0 + cc;
                    if (gc >= N) continue;
                    float vv = acc[mi][ni][rr * 2 + cc];
                    if (bias) vv += bias[gc];
                    if (flags & 1) vv = vv > 0.f ? vv : 0.01f * vv;
                    if (addp) vv = vv * scale + addp[(size_t)gr * ldadd + gc];
                    Cb[(size_t)gr * ldc + gc] = vv;
                }
            }
        }
    }
}

__device__ __forceinline__ void atomicMaxF(float* addr, float v)
{
    if (v >= 0.f) atomicMax((int*)addr, __float_as_int(v));
    else          atomicMin((unsigned int*)addr, __float_as_uint(v));
}

// x = 0.25*(p0+p1+p2+p3) + skip  (skip lives in uall); optionally fused pooling
__global__ void combine4_k(const float* __restrict__ part,
                           const float* __restrict__ uall, float* __restrict__ x,
                           const int* __restrict__ batch, float* __restrict__ feat,
                           int do_pool)
{
    int i = blockIdx.x * blockDim.x + threadIdx.x;
    if (i >= NN * DH) return;
    int n = i >> 8, c = i & 255;
    float s = part[i] + part[NN * DH + i] + part[2 * NN * DH + i] + part[3 * NN * DH + i];
    float v = 0.25f * s + uall[(size_t)n * WALLN + OFF_SKIP + c];
    x[i] = v;
    if (do_pool) {
        int b = batch[n];
        atomicAdd(&feat[b * FEATD + 512 + c], v);
        atomicMaxF(&feat[b * FEATD + 256 + c], v);
    }
}

// dst = act(sum_z part[z] + bias)  over M*N elements
__global__ void combine_mlp_k(const float* __restrict__ part,
                              const float* __restrict__ bias, float* __restrict__ dst,
                              int M, int N, int slices, int act)
{
    int i = blockIdx.x * blockDim.x + threadIdx.x;
    if (i >= M * N) return;
    int c = i % N;
    float s = 0.f;
    for (int z = 0; z < slices; z++) s += part[(size_t)z * M * N + i];
    s += bias[c];
    if (act) s = s > 0.f ? s : 0.01f * s;
    dst[i] = s;
}

// ---------------- fp32 sgemm with optional split-K ---------------------------
__global__ void sgemm_k(const float* __restrict__ A, const float* __restrict__ B,
                        const float* __restrict__ bias, float* __restrict__ C,
                        int M, int K, int Nn, int ldc, int act, int kslices)
{
    __shared__ float As[8][128];
    __shared__ float Bs[8][128];
    const int tid = threadIdx.x;
    const int row0 = blockIdx.x * 128;
    const int col0 = blockIdx.y * 128;
    const int ty = tid >> 4;
    const int tx = tid & 15;

    const int kper = K / kslices;
    const float* Ab = A + (size_t)blockIdx.z * kper;
    const float* Bb = B + (size_t)blockIdx.z * kper * Nn;
    float* Cb       = C + (size_t)blockIdx.z * M * ldc;

    float acc[8][8];
#pragma unroll
    for (int i = 0; i < 8; i++)
#pragma unroll
        for (int j = 0; j < 8; j++) acc[i][j] = 0.f;

    for (int k0 = 0; k0 < kper; k0 += 8) {
#pragma unroll
        for (int i = 0; i < 4; i++) {
            int idx = tid + i * 256;
            int r = idx >> 3, c = idx & 7;
            int gr = row0 + r, gc = k0 + c;
            As[c][r] = (gr < M && gc < kper) ? Ab[(size_t)gr * K + gc] : 0.f;
        }
#pragma unroll
        for (int i = 0; i < 4; i++) {
            int idx = tid + i * 256;
            int r = idx >> 7, c = idx & 127;
            int gr = k0 + r, gc = col0 + c;
            Bs[r][c] = (gr < kper && gc < Nn) ? Bb[(size_t)gr * Nn + gc] : 0.f;
        }
        __syncthreads();
#pragma unroll
        for (int kk = 0; kk < 8; kk++) {
            float a[8], b[8];
#pragma unroll
            for (int i = 0; i < 8; i++) a[i] = As[kk][ty * 8 + i];
#pragma unroll
            for (int j = 0; j < 8; j++) b[j] = Bs[kk][tx * 8 + j];
#pragma unroll
            for (int i = 0; i < 8; i++)
#pragma unroll
                for (int j = 0; j < 8; j++) acc[i][j] += a[i] * b[j];
        }
        __syncthreads();
    }

#pragma unroll
    for (int i = 0; i < 8; i++) {
        int gr = row0 + ty * 8 + i;
        if (gr >= M) continue;
#pragma unroll
        for (int j = 0; j < 8; j++) {
            int gc = col0 + tx * 8 + j;
            if (gc >= Nn) continue;
            float v = acc[i][j];
            if (bias) v += bias[gc];
            if (act)  v = v > 0.f ? v : 0.01f * v;
            Cb[(size_t)gr * ldc + gc] = v;
        }
    }
}

// ---------------- edge MLP layer 1: 4 edges per block ------------------------
__global__ __launch_bounds__(256) void edge1_k(const float* __restrict__ ea_attr,
                                               const float* __restrict__ w1,
                                               const float* __restrict__ b1,
                                               float* __restrict__ h)
{
    __shared__ float sw1[14 * 128];
    __shared__ float sb1[128];
    int tid = threadIdx.x;
    for (int i = tid; i < 14 * 128; i += 256) sw1[i] = w1[i];
    if (tid < 128) sb1[tid] = b1[tid];
    __syncthreads();

    int n = tid & 127;
#pragma unroll
    for (int q = 0; q < 2; q++) {
        int e = blockIdx.x * 4 + (tid >> 7) + q * 2;
        const float* arow = ea_attr + (size_t)e * 14;
        float acc = sb1[n];
#pragma unroll
        for (int k = 0; k < 14; k++) acc += arow[k] * sw1[k * 128 + n];
        acc = acc > 0.f ? acc : 0.01f * acc;
        h[(size_t)e * 128 + n] = acc;
    }
}

// ---------------- weight prep: Wqk_h=Wq_h@Wk_h^T, Wqe_h=Wq_h@We_h^T ----------
__global__ __launch_bounds__(256) void wprep_k(const float* __restrict__ wq_l,
                                               const float* __restrict__ wk_l,
                                               const float* __restrict__ we_l,
                                               float* __restrict__ wall)
{
    int z = blockIdx.z;
    int h = z >> 1, which = z & 1;
    const float* A = wq_l + h * 256;
    const float* B = (which ? we_l : wk_l) + h * 256;
    float* C = wall + (which ? OFF_QW : OFF_U) + h * 256;

    __shared__ float As[16][64];
    __shared__ float Bs[16][64];
    int tid = threadIdx.x;
    int ty = tid >> 4, tx = tid & 15;
    float acc[4][4];
#pragma unroll
    for (int i = 0; i < 4; i++)
#pragma unroll
        for (int j = 0; j < 4; j++) acc[i][j] = 0.f;

    for (int k0 = 0; k0 < 256; k0 += 16) {
        int m = tid >> 2, kq = tid & 3;
        float4 a4 = *(const float4*)(A + (size_t)(blockIdx.x * 64 + m) * 1024 + k0 + kq * 4);
        As[kq * 4 + 0][m] = a4.x; As[kq * 4 + 1][m] = a4.y;
        As[kq * 4 + 2][m] = a4.z; As[kq * 4 + 3][m] = a4.w;
        float4 b4 = *(const float4*)(B + (size_t)(blockIdx.y * 64 + m) * 1024 + k0 + kq * 4);
        Bs[kq * 4 + 0][m] = b4.x; Bs[kq * 4 + 1][m] = b4.y;
        Bs[kq * 4 + 2][m] = b4.z; Bs[kq * 4 + 3][m] = b4.w;
        __syncthreads();
#pragma unroll
        for (int kk = 0; kk < 16; kk++) {
            float a[4], b[4];
#pragma unroll
            for (int i = 0; i < 4; i++) a[i] = As[kk][ty * 4 + i];
#pragma unroll
            for (int j = 0; j < 4; j++) b[j] = Bs[kk][tx * 4 + j];
#pragma unroll
            for (int i = 0; i < 4; i++)
#pragma unroll
                for (int j = 0; j < 4; j++) acc[i][j] += a[i] * b[j];
        }
        __syncthreads();
    }
#pragma unroll
    for (int i = 0; i < 4; i++)
#pragma unroll
        for (int j = 0; j < 4; j++)
            C[(size_t)(blockIdx.x * 64 + ty * 4 + i) * WALLN + blockIdx.y * 64 + tx * 4 + j] = acc[i][j];
}

// wall[:,2048:2304]=wskip;  wst2[h*256+d,c]=wv[d,h*256+c]; wst2[1024+h*256+d,c]=we[d,h*256+c]
__global__ void pack_k(const float* __restrict__ wv_l, const float* __restrict__ ws_l,
                       const float* __restrict__ we_l, float* __restrict__ wall,
                       float* __restrict__ wst2)
{
    int i = blockIdx.x * blockDim.x + threadIdx.x;
    if (i < DH * DH) {
        int r = i >> 8, c = i & 255;
        wall[(size_t)r * WALLN + OFF_SKIP + c] = ws_l[r * 256 + c];
    }
    if (i < 2048 * DH) {
        int r = i >> 8, c = i & 255;
        if (r < 1024) {
            int h = r >> 8, d = r & 255;
            wst2[i] = wv_l[d * 1024 + h * 256 + c];
        } else {
            int r2 = r - 1024;
            int h = r2 >> 8, d = r2 & 255;
            wst2[i] = we_l[d * 1024 + h * 256 + c];
        }
    }
}

// ---------------- CSR build --------------------------------------------------
__global__ void zero_int_k(int* p, int n)
{
    int i = blockIdx.x * blockDim.x + threadIdx.x;
    if (i < n) p[i] = 0;
}

__global__ void deg_k(const int* __restrict__ tgt, int* __restrict__ deg)
{
    int e = blockIdx.x * blockDim.x + threadIdx.x;
    if (e < NE) atomicAdd(&deg[tgt[e]], 1);
}

__global__ __launch_bounds__(1024) void scan_k(const int* __restrict__ deg,
                                               int* __restrict__ off)
{
    __shared__ int part[1024];
    int tid = threadIdx.x;
    const int per = (NN + 1023) / 1024;
    int base = tid * per;
    int s = 0;
    for (int i = 0; i < per; i++) {
        int idx = base + i;
        if (idx < NN) s += deg[idx];
    }
    part[tid] = s;
    __syncthreads();
    for (int o = 1; o < 1024; o <<= 1) {
        int v = (tid >= o) ? part[tid - o] : 0;
        __syncthreads();
        part[tid] += v;
        __syncthreads();
    }
    int run = part[tid] - s;
    for (int i = 0; i < per; i++) {
        int idx = base + i;
        if (idx < NN) { off[idx] = run; run += deg[idx]; }
    }
    if (tid == 1023) off[NN] = part[1023];
}

__global__ void fillperm_k(const int* __restrict__ tgt, int* __restrict__ cur,
                           int* __restrict__ perm)
{
    int e = blockIdx.x * blockDim.x + threadIdx.x;
    if (e >= NE) return;
    int pos = atomicAdd(&cur[tgt[e]], 1);
    perm[pos] = e;
}

// ---------------- helpers ----------------------------------------------------
__global__ void fill_k(float* p, float v, int n)
{
    int i = blockIdx.x * blockDim.x + threadIdx.x;
    if (i < n) p[i] = v;
}

// vectorized embedding: one float4 per thread
__global__ void embed_k(const int* __restrict__ ids, const float* __restrict__ emb,
                        float* __restrict__ x)
{
    int i = blockIdx.x * blockDim.x + threadIdx.x;
    if (i >= NN * 64) return;
    int n = i >> 6, c4 = i & 63;
    ((float4*)x)[i] = ((const float4*)(emb + (size_t)ids[n] * DH))[c4];
}

// ---------------- fused per-target edge pipeline -----------------------------
__global__ __launch_bounds__(256) void edge_fused_k(
    const int* __restrict__ off, const int* __restrict__ perm,
    const int* __restrict__ src, const float* __restrict__ uall,
    const float* __restrict__ x, const float* __restrict__ ea,
    float* __restrict__ galpha, float* __restrict__ wcomb)
{
    __shared__ float su[1024];
    __shared__ float sqw[1024];
    __shared__ float sx[RCAP * 256];
    __shared__ float se[RCAP * 256];
    __shared__ float sal[CAP * 4];
    __shared__ int   sed[CAP];
    __shared__ int   ssrc[CAP];

    const int t   = blockIdx.x;
    const int tid = threadIdx.x;
    const int b   = off[t];
    const int deg = off[t + 1] - b;

    const float* ub = uall + (size_t)t * WALLN;
    ((float4*)su)[tid]  = ((const float4*)(ub + OFF_U))[tid];
    ((float4*)sqw)[tid] = ((const float4*)(ub + OFF_QW))[tid];
    __syncthreads();

    const int warp = tid >> 5, lane = tid & 31;
    for (int j = warp; j < deg; j += 8) {
        int e = perm[b + j];
        int s = src[e];
        if (lane == 0 && j < CAP) { sed[j] = e; ssrc[j] = s; }
        const float4* xp = (const float4*)(x + (size_t)s * 256);
        const float4* ep = (const float4*)(ea + (size_t)e * 256);
        float4 xv0 = xp[lane], xv1 = xp[lane + 32];
        float4 ev0 = ep[lane], ev1 = ep[lane + 32];
        if (j < RCAP) {
            ((float4*)(sx + j * 256))[lane]      = xv0;
            ((float4*)(sx + j * 256))[lane + 32] = xv1;
            ((float4*)(se + j * 256))[lane]      = ev0;
            ((float4*)(se + j * 256))[lane + 32] = ev1;
        }
        float a[4];
#pragma unroll
        for (int h = 0; h < 4; h++) {
            const float4* up = (const float4*)(su + h * 256);
            const float4* qp = (const float4*)(sqw + h * 256);
            float4 u0 = up[lane], u1 = up[lane + 32];
            float4 q0 = qp[lane], q1 = qp[lane + 32];
            float acc = u0.x * xv0.x + u0.y * xv0.y + u0.z * xv0.z + u0.w * xv0.w
                      + u1.x * xv1.x + u1.y * xv1.y + u1.z * xv1.z + u1.w * xv1.w
                      + q0.x * ev0.x + q0.y * ev0.y + q0.z * ev0.z + q0.w * ev0.w
                      + q1.x * ev1.x + q1.y * ev1.y + q1.z * ev1.z + q1.w * ev1.w;
#pragma unroll
            for (int o = 16; o; o >>= 1) acc += __shfl_xor_sync(0xffffffffu, acc, o);
            a[h] = acc * 0.0625f;
        }
        if (lane == 0) {
            if (j < CAP) {
                sal[j * 4 + 0] = a[0]; sal[j * 4 + 1] = a[1];
                sal[j * 4 + 2] = a[2]; sal[j * 4 + 3] = a[3];
            } else {
                galpha[e * 4 + 0] = a[0]; galpha[e * 4 + 1] = a[1];
                galpha[e * 4 + 2] = a[2]; galpha[e * 4 + 3] = a[3];
            }
        }
    }
    __syncthreads();

    if (tid < 4 && deg > 0) {
        int h = tid;
        float mx = -INFINITY;
        for (int j = 0; j < deg; j++) {
            float v = (j < CAP) ? sal[j * 4 + h] : galpha[perm[b + j] * 4 + h];
            mx = fmaxf(mx, v);
        }
        float ssum = 0.f;
        for (int j = 0; j < deg; j++) {
            float v = (j < CAP) ? sal[j * 4 + h] : galpha[perm[b + j] * 4 + h];
            ssum += __expf(v - mx);
        }
        float inv = 1.f / (ssum + 1e-16f);
        for (int j = 0; j < deg; j++) {
            if (j < CAP) {
                sal[j * 4 + h] = __expf(sal[j * 4 + h] - mx) * inv;
            } else {
                int e = perm[b + j];
                galpha[e * 4 + h] = __expf(galpha[e * 4 + h] - mx) * inv;
            }
        }
    }
    __syncthreads();

    const int d = tid;
    float aX[4] = {0.f, 0.f, 0.f, 0.f};
    float aE[4] = {0.f, 0.f, 0.f, 0.f};

    for (int j = 0; j < deg; j++) {
        float a0, a1, a2, a3;
        if (j < CAP) {
            a0 = sal[j * 4 + 0]; a1 = sal[j * 4 + 1];
            a2 = sal[j * 4 + 2]; a3 = sal[j * 4 + 3];
        } else {
            int e = perm[b + j];
            a0 = galpha[e * 4 + 0]; a1 = galpha[e * 4 + 1];
            a2 = galpha[e * 4 + 2]; a3 = galpha[e * 4 + 3];
        }
        float xv, ev;
        if (j < RCAP) {
            xv = sx[j * 256 + d];
            ev = se[j * 256 + d];
        } else {
            int e = (j < CAP) ? sed[j] : perm[b + j];
            int s = (j < CAP) ? ssrc[j] : src[e];
            xv = x[(size_t)s * 256 + d];
            ev = ea[(size_t)e * 256 + d];
        }
        aX[0] += a0 * xv; aX[1] += a1 * xv; aX[2] += a2 * xv; aX[3] += a3 * xv;
        aE[0] += a0 * ev; aE[1] += a1 * ev; aE[2] += a2 * ev; aE[3] += a3 * ev;
    }
    float* wrow = wcomb + (size_t)t * 2048;
#pragma unroll
    for (int h = 0; h < 4; h++) {
        wrow[h * 256 + d]        = aX[h];
        wrow[1024 + h * 256 + d] = aE[h];
    }
}

__global__ void cnt_k(const int* __restrict__ batch, float* __restrict__ cnt)
{
    int n = blockIdx.x * blockDim.x + threadIdx.x;
    if (n < NN) atomicAdd(&cnt[batch[n]], 1.f);
}

__global__ void pool_init_k(float* __restrict__ feat)
{
    int i = blockIdx.x * blockDim.x + threadIdx.x;
    if (i >= NB * 512) return;
    int b = i >> 9, c = i & 511;
    feat[b * FEATD + 256 + c] = (c < 256) ? __int_as_float(0xff800000u) : 0.f;
}

__global__ void meanpool_k(float* __restrict__ feat, const float* __restrict__ cnt)
{
    int i = blockIdx.x * blockDim.x + threadIdx.x;
    if (i >= NB * 256) return;
    int b = i >> 8, c = i & 255;
    feat[b * FEATD + c] = feat[b * FEATD + 512 + c] / cnt[b];
}

// ---------------- launch -----------------------------------------------------
static inline dim3 g128(int M, int Nn) { return dim3((M + 127) / 128, (Nn + 127) / 128); }

extern "C" void kernel_launch(void* const* d_in, const int* in_sizes, int n_in,
                              void* d_out, int out_size)
{
    const int*   x_ids    = (const int*)  d_in[0];
    const int*   eidx     = (const int*)  d_in[1];
    const int*   batch    = (const int*)  d_in[2];
    const float* edge_attr= (const float*)d_in[3];
    const float* energies = (const float*)d_in[4];
    const float* node_emb = (const float*)d_in[5];
    const float* ew1      = (const float*)d_in[6];
    const float* eb1      = (const float*)d_in[7];
    const float* ew2      = (const float*)d_in[8];
    const float* eb2      = (const float*)d_in[9];
    const float* wq       = (const float*)d_in[10];
    const float* wk       = (const float*)d_in[11];
    const float* wv       = (const float*)d_in[12];
    const float* we       = (const float*)d_in[13];
    const float* wskip    = (const float*)d_in[14];
    const float* fce_w1   = (const float*)d_in[15];
    const float* fce_b1   = (const float*)d_in[16];
    const float* fce_w2   = (const float*)d_in[17];
    const float* fce_b2   = (const float*)d_in[18];
    const float* fc_w1    = (const float*)d_in[19];
    const float* fc_b1    = (const float*)d_in[20];
    const float* fc_w2    = (const float*)d_in[21];
    const float* fc_b2    = (const float*)d_in[22];
    float* out = (float*)d_out;

    const int* src = eidx;
    const int* tgt = eidx + NE;

    float *x, *h, *ea, *uall, *alpha, *wcomb, *part, *feat, *cnt, *en1, *fc1;
    float *wallb, *wst2b;
    int *deg, *off, *cur, *perm;
    cudaGetSymbolAddress((void**)&x,     g_x);
    cudaGetSymbolAddress((void**)&h,     g_h);
    cudaGetSymbolAddress((void**)&ea,    g_ea);
    cudaGetSymbolAddress((void**)&wallb, g_wall);
    cudaGetSymbolAddress((void**)&wst2b, g_wst2);
    cudaGetSymbolAddress((void**)&uall,  g_uall);
    cudaGetSymbolAddress((void**)&alpha, g_alpha);
    cudaGetSymbolAddress((void**)&wcomb, g_wcomb);
    cudaGetSymbolAddress((void**)&part,  g_part);
    cudaGetSymbolAddress((void**)&feat,  g_feat);
    cudaGetSymbolAddress((void**)&cnt,   g_cnt);
    cudaGetSymbolAddress((void**)&en1,   g_en1);
    cudaGetSymbolAddress((void**)&fc1,   g_fc1);
    cudaGetSymbolAddress((void**)&deg,   g_deg);
    cudaGetSymbolAddress((void**)&off,   g_off);
    cudaGetSymbolAddress((void**)&cur,   g_cur);
    cudaGetSymbolAddress((void**)&perm,  g_perm);

    float* wall[3]  = { wallb, wallb + (size_t)DH * WALLN, wallb + 2 * (size_t)DH * WALLN };
    float* wst2[3]  = { wst2b, wst2b + (size_t)2048 * DH,  wst2b + 2 * (size_t)2048 * DH };

    cudaStream_t s2, s3;
    cudaStreamCreateWithFlags(&s2, cudaStreamNonBlocking);
    cudaStreamCreateWithFlags(&s3, cudaStreamNonBlocking);
    cudaEvent_t evFork, evL[3], evEA, evEN, evCSR, evPI;
    cudaEventCreateWithFlags(&evFork, cudaEventDisableTiming);
    for (int l = 0; l < 3; l++) cudaEventCreateWithFlags(&evL[l], cudaEventDisableTiming);
    cudaEventCreateWithFlags(&evEA, cudaEventDisableTiming);
    cudaEventCreateWithFlags(&evEN, cudaEventDisableTiming);
    cudaEventCreateWithFlags(&evCSR, cudaEventDisableTiming);
    cudaEventCreateWithFlags(&evPI, cudaEventDisableTiming);

    // main: node embedding (vectorized)
    embed_k<<<(NN * 64 + 255) / 256, 256>>>(x_ids, node_emb, x);
    cudaEventRecord(evFork, 0);
    cudaStreamWaitEvent(s2, evFork, 0);
    cudaStreamWaitEvent(s3, evFork, 0);

    // s2: layer-0 weight prep
    wprep_k<<<dim3(4, 4, 8), 256, 0, s2>>>(wq, wk, we, wall[0]);
    pack_k<<<(2048 * DH + 255) / 256, 256, 0, s2>>>(wv, wskip, we, wall[0], wst2[0]);
    cudaEventRecord(evL[0], s2);

    // main: uall layer 0
    cudaStreamWaitEvent(0, evL[0], 0);
    tgemm<<<g128(NN, WALLN), 256>>>(x, wall[0], nullptr, uall,
                                    NN, 256, WALLN, 256, WALLN, WALLN, 0,
                                    nullptr, 0, 1.f, 1);

    // s3: CSR build, then pooling preamble (batch-only dependencies)
    zero_int_k<<<(NN + 255) / 256, 256, 0, s3>>>(deg, NN);
    deg_k<<<(NE + 255) / 256, 256, 0, s3>>>(tgt, deg);
    scan_k<<<1, 1024, 0, s3>>>(deg, off);
    cudaMemcpyAsync(cur, off, NN * sizeof(int), cudaMemcpyDeviceToDevice, s3);
    fillperm_k<<<(NE + 255) / 256, 256, 0, s3>>>(tgt, cur, perm);
    cudaEventRecord(evCSR, s3);
    pool_init_k<<<(NB * 512 + 255) / 256, 256, 0, s3>>>(feat);
    fill_k<<<1, NB, 0, s3>>>(cnt, 0.f, NB);
    cnt_k<<<(NN + 255) / 256, 256, 0, s3>>>(batch, cnt);
    cudaEventRecord(evPI, s3);

    // s2: edge MLP chain, remaining weight preps, energies MLP
    edge1_k<<<NE / 4, 256, 0, s2>>>(edge_attr, ew1, eb1, h);
    tgemm<<<g128(NE, 256), 256, 0, s2>>>(h, ew2, eb2, ea, NE, 128, 256, 128, 256, 256, 0,
                                         nullptr, 0, 1.f, 1);
    cudaEventRecord(evEA, s2);
    for (int l = 1; l < 3; l++) {
        wprep_k<<<dim3(4, 4, 8), 256, 0, s2>>>(wq + (size_t)l * DH * HC,
                                               wk + (size_t)l * DH * HC,
                                               we + (size_t)l * DH * HC, wall[l]);
        pack_k<<<(2048 * DH + 255) / 256, 256, 0, s2>>>(wv + (size_t)l * DH * HC,
                                                        wskip + (size_t)l * DH * DH,
                                                        we + (size_t)l * DH * HC,
                                                        wall[l], wst2[l]);
        cudaEventRecord(evL[l], s2);
    }
    sgemm_k<<<g128(NB, 256), 256, 0, s2>>>(energies, fce_w1, fce_b1, en1,
                                           NB, 201, 256, 256, 1, 1);
    sgemm_k<<<g128(NB, 128), 256, 0, s2>>>(en1, fce_w2, fce_b2, feat + 768,
                                           NB, 256, 128, FEATD, 0, 1);
    cudaEventRecord(evEN, s2);

    // main: layers
    cudaStreamWaitEvent(0, evEA, 0);
    cudaStreamWaitEvent(0, evCSR, 0);
    for (int l = 0; l < 3; l++) {
        if (l > 0) {
            cudaStreamWaitEvent(0, evL[l], 0);
            tgemm<<<g128(NN, WALLN), 256>>>(x, wall[l], nullptr, uall,
                                            NN, 256, WALLN, 256, WALLN, WALLN, 0,
                                            nullptr, 0, 1.f, 1);
        }
        edge_fused_k<<<NN, 256>>>(off, perm, src, uall, x, ea, alpha, wcomb);
        {
            dim3 g = g128(NN, DH);
            g.z = KSPLIT;
            tgemm<<<g, 256>>>(wcomb, wst2[l], nullptr, part,
                              NN, 2048, 256, 2048, 256, 256, 0,
                              nullptr, 0, 1.f, KSPLIT);
        }
        if (l == 2) cudaStreamWaitEvent(0, evPI, 0);   // feat init + cnt ready
        combine4_k<<<(NN * DH + 255) / 256, 256>>>(part, uall, x, batch, feat,
                                                   l == 2 ? 1 : 0);
    }

    // pooling epilogue (sum/max fused into last combine)
    meanpool_k<<<(NB * 256 + 255) / 256, 256>>>(feat, cnt);

    // final MLP (split-K both; fc1 8 slices: K=896 -> 8 x 112)
    cudaStreamWaitEvent(0, evEN, 0);
    {
        dim3 g1(1, 8, 8);
        tgemm<<<g1, 256>>>(feat, fc_w1, nullptr, part,
                           NB, FEATD, 1024, FEATD, 1024, 1024, 0,
                           nullptr, 0, 1.f, 8);
        combine_mlp_k<<<(NB * 1024 + 255) / 256, 256>>>(part, fc_b1, fc1,
                                                        NB, 1024, 8, 1);
        dim3 g2(1, 7, 8);
        sgemm_k<<<g2, 256>>>(fc1, fc_w2, nullptr, part,
                             NB, 1024, 804, 804, 0, 8);
        combine_mlp_k<<<(NB * 804 + 255) / 256, 256>>>(part, fc_b2, out,
                                                       NB, 804, 8, 0);
    }

    cudaEventDestroy(evFork);
    for (int l = 0; l < 3; l++) cudaEventDestroy(evL[l]);
    cudaEventDestroy(evEA);
    cudaEventDestroy(evEN);
    cudaEventDestroy(evCSR);
    cudaEventDestroy(evPI);
    cudaStreamDestroy(s2);
    cudaStreamDestroy(s3);
}